// round 5
// baseline (speedup 1.0000x reference)
#include <cuda_runtime.h>
#include <math.h>

#define Nn 50000
#define Ee 800000
#define ETOT 850000
#define Hh 96
#define Gg 64
#define NCLS 4
#define BNEPS 1e-5f

// ---------------- device scratch ----------------
__device__ float g_h[Nn * Hh];
__device__ float g_id[Nn * Hh];
__device__ float g_hp[Nn * Hh];
__device__ float g_tmp[Nn * Hh];
__device__ float g_ss[Nn], g_sd[Nn];
__device__ float g_ew[ETOT];
__device__ int   g_deg[Nn];
__device__ int   g_rs[Nn + 1];
__device__ int   g_cur[Nn];
__device__ int   g_csr[ETOT];
__device__ float g_bnsum[3 * Hh], g_bnsq[3 * Hh];
__device__ float g_pooled[Gg * Hh];
__device__ float g_cnt[Gg];

__device__ __forceinline__ float lrelu01(float v) { return v >= 0.f ? v : 0.01f * v; }

// ---------------- zero / init ----------------
__global__ void zero_k() {
    int i = blockIdx.x * blockDim.x + threadIdx.x;
    int stride = gridDim.x * blockDim.x;
    for (int j = i; j < Nn; j += stride) g_deg[j] = 0;
    if (i < Gg * Hh) g_pooled[i] = 0.f;
    if (i < Gg) g_cnt[i] = 0.f;
    if (i < 3 * Hh) { g_bnsum[i] = 0.f; g_bnsq[i] = 0.f; }
}

// ---------------- CSR build ----------------
__global__ void count_k(const int* __restrict__ ei) {
    int i = blockIdx.x * blockDim.x + threadIdx.x;
    if (i >= ETOT) return;
    int d = (i < Ee) ? ei[Ee + i] : (i - Ee);
    atomicAdd(&g_deg[d], 1);
}

__global__ void scan_k() {
    __shared__ int part[1024];
    int t = threadIdx.x;
    const int CH = (Nn + 1023) / 1024;
    int base = t * CH;
    int s = 0;
    for (int i = 0; i < CH; i++) {
        int idx = base + i;
        if (idx < Nn) s += g_deg[idx];
    }
    part[t] = s;
    __syncthreads();
    for (int off = 1; off < 1024; off <<= 1) {
        int v = (t >= off) ? part[t - off] : 0;
        __syncthreads();
        part[t] += v;
        __syncthreads();
    }
    int run = (t == 0) ? 0 : part[t - 1];
    for (int i = 0; i < CH; i++) {
        int idx = base + i;
        if (idx < Nn) {
            g_rs[idx] = run;
            g_cur[idx] = run;
            run += g_deg[idx];
        }
    }
    if (t == blockDim.x - 1) g_rs[Nn] = part[blockDim.x - 1];
}

__global__ void scatter_k(const int* __restrict__ ei) {
    int i = blockIdx.x * blockDim.x + threadIdx.x;
    if (i >= ETOT) return;
    int sN, dN;
    if (i < Ee) { sN = ei[i]; dN = ei[Ee + i]; }
    else        { sN = i - Ee; dN = i - Ee; }
    int pos = atomicAdd(&g_cur[dN], 1);
    g_csr[pos] = sN;
}

// ---------------- GEMM: C[M,96] = act(A'[M,K] @ W[K,96] + bias) ----------------
// tile 128x96, 384 threads, micro-tile 8x4 (plain FFMA — R2-proven core).
// MODE==1: A' = lrelu(bn(A)) + A2 fused on A-load (K must be 96).
// SCORES==1: also emits per-row ss = row.a_s, sd = row.a_d.
template <int ACT, int MODE, int DUP, int SCORES>
__global__ __launch_bounds__(384, 2) void gemm128(
    const float* __restrict__ A, const float* __restrict__ A2,
    const float* __restrict__ gma, const float* __restrict__ bta,
    const float* __restrict__ sumP, const float* __restrict__ sqP,
    const float* __restrict__ W, const float* __restrict__ bias,
    const float* __restrict__ as_, const float* __restrict__ ad_,
    float* __restrict__ ssO, float* __restrict__ sdO,
    float* __restrict__ C, float* __restrict__ C2, int M, int K)
{
    __shared__ float Ash[32][132];   // [k][m]
    __shared__ float Wsh[32][96];
    __shared__ float s_sc[96], s_sh[96];
    __shared__ float sS[128], sD[128];
    int tid = threadIdx.x;
    if (MODE == 1) {
        if (tid < 96) {
            float mu = sumP[tid] * (1.f / Nn);
            float var = sqP[tid] * (1.f / Nn) - mu * mu;
            float is = rsqrtf(var + BNEPS);
            float gv = gma[tid];
            s_sc[tid] = gv * is;
            s_sh[tid] = bta[tid] - mu * gv * is;
        }
        __syncthreads();
    }
    if (SCORES) {
        if (tid < 128) { sS[tid] = 0.f; sD[tid] = 0.f; }
    }
    int cg = tid % 24;               // cols cg*4..+3
    int rg = tid / 24;               // rows rg*8..+7
    int rowBase = blockIdx.x * 128;
    float acc[8][4] = {};
    for (int kc = 0; kc < K; kc += 32) {
        for (int idx = tid; idx < 1024; idx += 384) {
            int m = idx >> 3, kq = idx & 7;
            int r = rowBase + m;
            float4 v = make_float4(0.f, 0.f, 0.f, 0.f);
            if (r < M) {
                v = *(const float4*)&A[r * K + kc + kq * 4];
                if (MODE == 1) {
                    float4 u = *(const float4*)&A2[r * K + kc + kq * 4];
                    int c = kc + kq * 4;
                    v.x = lrelu01(fmaf(v.x, s_sc[c + 0], s_sh[c + 0])) + u.x;
                    v.y = lrelu01(fmaf(v.y, s_sc[c + 1], s_sh[c + 1])) + u.y;
                    v.z = lrelu01(fmaf(v.z, s_sc[c + 2], s_sh[c + 2])) + u.z;
                    v.w = lrelu01(fmaf(v.w, s_sc[c + 3], s_sh[c + 3])) + u.w;
                }
            }
            int k0 = kq * 4;
            Ash[k0 + 0][m] = v.x;
            Ash[k0 + 1][m] = v.y;
            Ash[k0 + 2][m] = v.z;
            Ash[k0 + 3][m] = v.w;
        }
        #pragma unroll
        for (int j = 0; j < 8; j++) {
            int idx = tid + j * 384;
            int k = idx / 96, c = idx % 96;
            Wsh[k][c] = W[(kc + k) * 96 + c];
        }
        __syncthreads();
        #pragma unroll
        for (int k = 0; k < 32; k++) {
            float4 al = *(const float4*)&Ash[k][rg * 8];
            float4 ah = *(const float4*)&Ash[k][rg * 8 + 4];
            float4 w  = *(const float4*)&Wsh[k][cg * 4];
            float av[8] = {al.x, al.y, al.z, al.w, ah.x, ah.y, ah.z, ah.w};
            float wv[4] = {w.x, w.y, w.z, w.w};
            #pragma unroll
            for (int i = 0; i < 8; i++)
                #pragma unroll
                for (int j = 0; j < 4; j++)
                    acc[i][j] = fmaf(av[i], wv[j], acc[i][j]);
        }
        __syncthreads();
    }
    int c0 = cg * 4;
    float bv[4];
    #pragma unroll
    for (int j = 0; j < 4; j++) bv[j] = bias ? bias[c0 + j] : 0.f;
    float asv[4], adv[4];
    if (SCORES) {
        #pragma unroll
        for (int j = 0; j < 4; j++) { asv[j] = as_[c0 + j]; adv[j] = ad_[c0 + j]; }
    }
    int r0 = rowBase + rg * 8;
    #pragma unroll
    for (int i = 0; i < 8; i++) {
        int r = r0 + i;
        if (r < M) {
            if (SCORES) {
                float s1 = acc[i][0] * asv[0] + acc[i][1] * asv[1] + acc[i][2] * asv[2] + acc[i][3] * asv[3];
                float s2 = acc[i][0] * adv[0] + acc[i][1] * adv[1] + acc[i][2] * adv[2] + acc[i][3] * adv[3];
                atomicAdd(&sS[rg * 8 + i], s1);
                atomicAdd(&sD[rg * 8 + i], s2);
            }
            float v0 = acc[i][0] + bv[0];
            float v1 = acc[i][1] + bv[1];
            float v2 = acc[i][2] + bv[2];
            float v3 = acc[i][3] + bv[3];
            if (ACT) { v0 = lrelu01(v0); v1 = lrelu01(v1); v2 = lrelu01(v2); v3 = lrelu01(v3); }
            float4 o = make_float4(v0, v1, v2, v3);
            *(float4*)&C[r * 96 + c0] = o;
            if (DUP) *(float4*)&C2[r * 96 + c0] = o;
        }
    }
    if (SCORES) {
        __syncthreads();
        if (tid < 128) {
            int r = rowBase + tid;
            if (r < M) { ssO[r] = sS[tid]; sdO[r] = sD[tid]; }
        }
    }
}

// ---------------- GAT aggregation (warp/dst) + fused BN stats ----------------
// max-free softmax: scores are bounded (BN'd activations, small weights), no overflow.
__global__ void agg_k(const float* __restrict__ hp,
                      const float* __restrict__ ss, const float* __restrict__ sd,
                      const float* __restrict__ bias, float* __restrict__ out,
                      float* __restrict__ sumP, float* __restrict__ sqP)
{
    __shared__ float bs[96], bq[96];
    int tid = threadIdx.x;
    if (tid < 96) { bs[tid] = 0.f; bq[tid] = 0.f; }
    __syncthreads();
    int d = (blockIdx.x * blockDim.x + tid) >> 5;
    int lane = tid & 31;
    if (d < Nn) {
        int s0 = g_rs[d], s1e = g_rs[d + 1];
        float sdd = sd[d];
        // pass 1: denominator + cache numerators
        float denom = 0.f;
        for (int j = s0 + lane; j < s1e; j += 32) {
            int s = g_csr[j];
            float e = ss[s] + sdd;
            e = (e >= 0.f) ? e : 0.2f * e;
            float wv = __expf(e);
            g_ew[j] = wv;
            denom += wv;
        }
        #pragma unroll
        for (int o = 16; o; o >>= 1) denom += __shfl_xor_sync(0xffffffffu, denom, o);
        float inv = 1.f / denom;
        // pass 2: weighted feature aggregation
        float a0 = 0.f, a1 = 0.f, a2 = 0.f;
        for (int j = s0; j < s1e; j++) {
            int s = g_csr[j];
            float wgt = g_ew[j] * inv;
            const float* row = hp + s * 96;
            a0 = fmaf(wgt, row[lane], a0);
            a1 = fmaf(wgt, row[lane + 32], a1);
            a2 = fmaf(wgt, row[lane + 64], a2);
        }
        float v0 = a0 + bias[lane];
        float v1 = a1 + bias[lane + 32];
        float v2 = a2 + bias[lane + 64];
        out[d * 96 + lane]      = v0;
        out[d * 96 + lane + 32] = v1;
        out[d * 96 + lane + 64] = v2;
        atomicAdd(&bs[lane], v0);       atomicAdd(&bq[lane], v0 * v0);
        atomicAdd(&bs[lane + 32], v1);  atomicAdd(&bq[lane + 32], v1 * v1);
        atomicAdd(&bs[lane + 64], v2);  atomicAdd(&bq[lane + 64], v2 * v2);
    }
    __syncthreads();
    if (tid < 96) {
        atomicAdd(&sumP[tid], bs[tid]);
        atomicAdd(&sqP[tid], bq[tid]);
    }
}

// ---------------- fused BN-apply + Poincare expmap0 + segment pooling ----------------
__global__ void expool_k(const float* __restrict__ t, const float* __restrict__ idn,
                         const float* __restrict__ gma, const float* __restrict__ bta,
                         const float* __restrict__ sumP, const float* __restrict__ sqP,
                         const int* __restrict__ batch)
{
    __shared__ float sp[Gg * Hh];
    __shared__ float scn[Gg];
    __shared__ float s_sc[96], s_sh[96];
    if (threadIdx.x < 96) {
        int c = threadIdx.x;
        float mu = sumP[c] * (1.f / Nn);
        float var = sqP[c] * (1.f / Nn) - mu * mu;
        float is = rsqrtf(var + BNEPS);
        float gv = gma[c];
        s_sc[c] = gv * is;
        s_sh[c] = bta[c] - mu * gv * is;
    }
    for (int i = threadIdx.x; i < Gg * Hh; i += blockDim.x) sp[i] = 0.f;
    if (threadIdx.x < Gg) scn[threadIdx.x] = 0.f;
    __syncthreads();
    int lane = threadIdx.x & 31;
    int warp = (blockIdx.x * blockDim.x + threadIdx.x) >> 5;
    int nwarps = (gridDim.x * blockDim.x) >> 5;
    for (int n = warp; n < Nn; n += nwarps) {
        float v0 = lrelu01(fmaf(t[n * 96 + lane],      s_sc[lane],      s_sh[lane]))      + idn[n * 96 + lane];
        float v1 = lrelu01(fmaf(t[n * 96 + lane + 32], s_sc[lane + 32], s_sh[lane + 32])) + idn[n * 96 + lane + 32];
        float v2 = lrelu01(fmaf(t[n * 96 + lane + 64], s_sc[lane + 64], s_sh[lane + 64])) + idn[n * 96 + lane + 64];
        float q = v0 * v0 + v1 * v1 + v2 * v2;
        #pragma unroll
        for (int o = 16; o; o >>= 1) q += __shfl_xor_sync(0xffffffffu, q, o);
        float nrm = fmaxf(sqrtf(q), 1e-15f);
        float s = tanhf(nrm) / nrm;
        int g = batch[n];
        atomicAdd(&sp[g * 96 + lane], v0 * s);
        atomicAdd(&sp[g * 96 + lane + 32], v1 * s);
        atomicAdd(&sp[g * 96 + lane + 64], v2 * s);
        if (lane == 0) atomicAdd(&scn[g], 1.f);
    }
    __syncthreads();
    for (int i = threadIdx.x; i < Gg * Hh; i += blockDim.x) atomicAdd(&g_pooled[i], sp[i]);
    if (threadIdx.x < Gg) atomicAdd(&g_cnt[threadIdx.x], scn[threadIdx.x]);
}

// ---------------- head ----------------
__global__ void head_k(const float* __restrict__ fc3W, const float* __restrict__ fc3b,
                       const float* __restrict__ fc4W, const float* __restrict__ fc4b,
                       float* __restrict__ out)
{
    __shared__ float p[Gg * Hh];
    __shared__ float o1[Gg * 48];
    for (int i = threadIdx.x; i < Gg * Hh; i += blockDim.x) {
        int g = i / 96;
        p[i] = g_pooled[i] / fmaxf(g_cnt[g], 1.f);
    }
    __syncthreads();
    for (int i = threadIdx.x; i < Gg * 48; i += blockDim.x) {
        int g = i / 48, c = i % 48;
        float a = fc3b[c];
        for (int k = 0; k < 96; k++) a = fmaf(p[g * 96 + k], fc3W[k * 48 + c], a);
        o1[i] = lrelu01(a);
    }
    __syncthreads();
    for (int i = threadIdx.x; i < Gg * NCLS; i += blockDim.x) {
        int g = i / NCLS, c = i % NCLS;
        float a = fc4b[c];
        for (int k = 0; k < 48; k++) a = fmaf(o1[g * 48 + k], fc4W[k * NCLS + c], a);
        out[i] = a;
    }
}

// ---------------- launch ----------------
extern "C" void kernel_launch(void* const* d_in, const int* in_sizes, int n_in,
                              void* d_out, int out_size)
{
    const float* x     = (const float*)d_in[0];
    const int*   ei    = (const int*)d_in[1];
    const int*   batch = (const int*)d_in[2];
    const float* embW  = (const float*)d_in[3];
    const float* embB  = (const float*)d_in[4];
    const float* cW[3]  = {(const float*)d_in[5],  (const float*)d_in[9],  (const float*)d_in[13]};
    const float* cAS[3] = {(const float*)d_in[6],  (const float*)d_in[10], (const float*)d_in[14]};
    const float* cAD[3] = {(const float*)d_in[7],  (const float*)d_in[11], (const float*)d_in[15]};
    const float* cB[3]  = {(const float*)d_in[8],  (const float*)d_in[12], (const float*)d_in[16]};
    const float* fcW[2] = {(const float*)d_in[17], (const float*)d_in[19]};
    const float* fcB[2] = {(const float*)d_in[18], (const float*)d_in[20]};
    const float* bnG[3] = {(const float*)d_in[21], (const float*)d_in[23], (const float*)d_in[25]};
    const float* bnB[3] = {(const float*)d_in[22], (const float*)d_in[24], (const float*)d_in[26]};
    const float* fc3W = (const float*)d_in[27];
    const float* fc3b = (const float*)d_in[28];
    const float* fc4W = (const float*)d_in[29];
    const float* fc4b = (const float*)d_in[30];
    float* out = (float*)d_out;

    float *ph, *pid, *php, *ptmp, *pss, *psd, *pbs, *pbq;
    cudaGetSymbolAddress((void**)&ph,   g_h);
    cudaGetSymbolAddress((void**)&pid,  g_id);
    cudaGetSymbolAddress((void**)&php,  g_hp);
    cudaGetSymbolAddress((void**)&ptmp, g_tmp);
    cudaGetSymbolAddress((void**)&pss,  g_ss);
    cudaGetSymbolAddress((void**)&psd,  g_sd);
    cudaGetSymbolAddress((void**)&pbs,  g_bnsum);
    cudaGetSymbolAddress((void**)&pbq,  g_bnsq);

    const int EB = (ETOT + 255) / 256;
    const int GB = (Nn + 127) / 128;
    const int WB = (Nn * 32 + 255) / 256;

    // Fork: CSR build concurrent with embed GEMM. Streams/events intentionally
    // leaked (destroying them mid-capture would abort graph capture).
    cudaStream_t s1;
    cudaStreamCreateWithFlags(&s1, cudaStreamNonBlocking);
    cudaEvent_t evFork, evJoin;
    cudaEventCreateWithFlags(&evFork, cudaEventDisableTiming);
    cudaEventCreateWithFlags(&evJoin, cudaEventDisableTiming);

    cudaEventRecord(evFork, 0);
    cudaStreamWaitEvent(s1, evFork, 0);
    zero_k<<<256, 256, 0, s1>>>();
    count_k<<<EB, 256, 0, s1>>>(ei);
    scan_k<<<1, 1024, 0, s1>>>();
    scatter_k<<<EB, 256, 0, s1>>>(ei);
    cudaEventRecord(evJoin, s1);

    // embed: h = lrelu(x @ embW + embB); identity = h
    gemm128<1, 0, 1, 0><<<GB, 384>>>(x, nullptr, nullptr, nullptr, nullptr, nullptr,
                                     embW, embB, nullptr, nullptr, nullptr, nullptr,
                                     ph, pid, Nn, 256);

    for (int l = 0; l < 3; l++) {
        // hp = h @ cW  (+ fused attention scores)
        gemm128<0, 0, 0, 1><<<GB, 384>>>(ph, nullptr, nullptr, nullptr, nullptr, nullptr,
                                         cW[l], nullptr, cAS[l], cAD[l], pss, psd,
                                         php, nullptr, Nn, 96);
        if (l == 0) cudaStreamWaitEvent(0, evJoin, 0);   // CSR + zeroed BN slots ready
        agg_k<<<WB, 256>>>(php, pss, psd, cB[l], ptmp, pbs + l * Hh, pbq + l * Hh);
        if (l < 2) {
            // h = lrelu( (lrelu(bn(tmp)) + id) @ fcW + fcB ) — BN fused into A-load
            gemm128<1, 1, 0, 0><<<GB, 384>>>(ptmp, pid, bnG[l], bnB[l], pbs + l * Hh, pbq + l * Hh,
                                             fcW[l], fcB[l], nullptr, nullptr, nullptr, nullptr,
                                             ph, nullptr, Nn, 96);
        }
    }

    expool_k<<<160, 256>>>(ptmp, pid, bnG[2], bnB[2], pbs + 2 * Hh, pbq + 2 * Hh, batch);
    head_k<<<1, 256>>>(fc3W, fc3b, fc4W, fc4b, out);
}

// round 7
// speedup vs baseline: 1.1798x; 1.1798x over previous
#include <cuda_runtime.h>
#include <math.h>

#define Nn 50000
#define Ee 800000
#define ETOT 850000
#define Hh 96
#define Gg 64
#define NCLS 4
#define BNEPS 1e-5f

// ---------------- device scratch ----------------
__device__ float g_h[Nn * Hh];
__device__ float g_id[Nn * Hh];
__device__ float g_hp[Nn * Hh];
__device__ float g_tmp[Nn * Hh];
__device__ float g_ss[Nn], g_sd[Nn];
__device__ float g_ew[ETOT];
__device__ int   g_deg[Nn];
__device__ int   g_rs[Nn + 1];
__device__ int   g_cur[Nn];
__device__ int   g_csr[ETOT];
__device__ float g_bnsum[3 * Hh], g_bnsq[3 * Hh];
__device__ float g_pooled[Gg * Hh];
__device__ float g_cnt[Gg];

__device__ __forceinline__ float lrelu01(float v) { return v >= 0.f ? v : 0.01f * v; }

// ---------------- zero / init ----------------
__global__ void zero_k() {
    int i = blockIdx.x * blockDim.x + threadIdx.x;
    int stride = gridDim.x * blockDim.x;
    for (int j = i; j < Nn; j += stride) g_deg[j] = 0;
    if (i < Gg * Hh) g_pooled[i] = 0.f;
    if (i < Gg) g_cnt[i] = 0.f;
    if (i < 3 * Hh) { g_bnsum[i] = 0.f; g_bnsq[i] = 0.f; }
}

// ---------------- CSR build ----------------
__global__ void count_k(const int* __restrict__ ei) {
    int i = blockIdx.x * blockDim.x + threadIdx.x;
    if (i >= ETOT) return;
    int d = (i < Ee) ? ei[Ee + i] : (i - Ee);
    atomicAdd(&g_deg[d], 1);
}

__global__ void scan_k() {
    __shared__ int part[1024];
    int t = threadIdx.x;
    const int CH = (Nn + 1023) / 1024;
    int base = t * CH;
    int s = 0;
    for (int i = 0; i < CH; i++) {
        int idx = base + i;
        if (idx < Nn) s += g_deg[idx];
    }
    part[t] = s;
    __syncthreads();
    for (int off = 1; off < 1024; off <<= 1) {
        int v = (t >= off) ? part[t - off] : 0;
        __syncthreads();
        part[t] += v;
        __syncthreads();
    }
    int run = (t == 0) ? 0 : part[t - 1];
    for (int i = 0; i < CH; i++) {
        int idx = base + i;
        if (idx < Nn) {
            g_rs[idx] = run;
            g_cur[idx] = run;
            run += g_deg[idx];
        }
    }
    if (t == blockDim.x - 1) g_rs[Nn] = part[blockDim.x - 1];
}

__global__ void scatter_k(const int* __restrict__ ei) {
    int i = blockIdx.x * blockDim.x + threadIdx.x;
    if (i >= ETOT) return;
    int sN, dN;
    if (i < Ee) { sN = ei[i]; dN = ei[Ee + i]; }
    else        { sN = i - Ee; dN = i - Ee; }
    int pos = atomicAdd(&g_cur[dN], 1);
    g_csr[pos] = sN;
}

// ---------------- GEMM: C[M,96] = act(A'[M,K] @ W[K,96] + bias) ----------------
// tile 128x96, 384 threads, micro-tile 8x4 (plain FFMA — R2-proven core).
// MODE==1: A' = lrelu(bn(A)) + A2 fused on A-load (K must be 96).
template <int ACT, int MODE, int DUP>
__global__ __launch_bounds__(384, 2) void gemm128(
    const float* __restrict__ A, const float* __restrict__ A2,
    const float* __restrict__ gma, const float* __restrict__ bta,
    const float* __restrict__ sumP, const float* __restrict__ sqP,
    const float* __restrict__ W, const float* __restrict__ bias,
    float* __restrict__ C, float* __restrict__ C2, int M, int K)
{
    __shared__ float Ash[32][132];   // [k][m]
    __shared__ float Wsh[32][96];
    __shared__ float s_sc[96], s_sh[96];
    int tid = threadIdx.x;
    if (MODE == 1) {
        if (tid < 96) {
            float mu = sumP[tid] * (1.f / Nn);
            float var = sqP[tid] * (1.f / Nn) - mu * mu;
            float is = rsqrtf(var + BNEPS);
            float gv = gma[tid];
            s_sc[tid] = gv * is;
            s_sh[tid] = bta[tid] - mu * gv * is;
        }
        __syncthreads();
    }
    int cg = tid % 24;               // cols cg*4..+3
    int rg = tid / 24;               // rows rg*8..+7
    int rowBase = blockIdx.x * 128;
    float acc[8][4] = {};
    for (int kc = 0; kc < K; kc += 32) {
        for (int idx = tid; idx < 1024; idx += 384) {
            int m = idx >> 3, kq = idx & 7;
            int r = rowBase + m;
            float4 v = make_float4(0.f, 0.f, 0.f, 0.f);
            if (r < M) {
                v = *(const float4*)&A[r * K + kc + kq * 4];
                if (MODE == 1) {
                    float4 u = *(const float4*)&A2[r * K + kc + kq * 4];
                    int c = kc + kq * 4;
                    v.x = lrelu01(fmaf(v.x, s_sc[c + 0], s_sh[c + 0])) + u.x;
                    v.y = lrelu01(fmaf(v.y, s_sc[c + 1], s_sh[c + 1])) + u.y;
                    v.z = lrelu01(fmaf(v.z, s_sc[c + 2], s_sh[c + 2])) + u.z;
                    v.w = lrelu01(fmaf(v.w, s_sc[c + 3], s_sh[c + 3])) + u.w;
                }
            }
            int k0 = kq * 4;
            Ash[k0 + 0][m] = v.x;
            Ash[k0 + 1][m] = v.y;
            Ash[k0 + 2][m] = v.z;
            Ash[k0 + 3][m] = v.w;
        }
        #pragma unroll
        for (int j = 0; j < 8; j++) {
            int idx = tid + j * 384;
            int k = idx / 96, c = idx % 96;
            Wsh[k][c] = W[(kc + k) * 96 + c];
        }
        __syncthreads();
        #pragma unroll
        for (int k = 0; k < 32; k++) {
            float4 al = *(const float4*)&Ash[k][rg * 8];
            float4 ah = *(const float4*)&Ash[k][rg * 8 + 4];
            float4 w  = *(const float4*)&Wsh[k][cg * 4];
            float av[8] = {al.x, al.y, al.z, al.w, ah.x, ah.y, ah.z, ah.w};
            float wv[4] = {w.x, w.y, w.z, w.w};
            #pragma unroll
            for (int i = 0; i < 8; i++)
                #pragma unroll
                for (int j = 0; j < 4; j++)
                    acc[i][j] = fmaf(av[i], wv[j], acc[i][j]);
        }
        __syncthreads();
    }
    int c0 = cg * 4;
    float bv[4];
    #pragma unroll
    for (int j = 0; j < 4; j++) bv[j] = bias ? bias[c0 + j] : 0.f;
    int r0 = rowBase + rg * 8;
    #pragma unroll
    for (int i = 0; i < 8; i++) {
        int r = r0 + i;
        if (r < M) {
            float v0 = acc[i][0] + bv[0];
            float v1 = acc[i][1] + bv[1];
            float v2 = acc[i][2] + bv[2];
            float v3 = acc[i][3] + bv[3];
            if (ACT) { v0 = lrelu01(v0); v1 = lrelu01(v1); v2 = lrelu01(v2); v3 = lrelu01(v3); }
            float4 o = make_float4(v0, v1, v2, v3);
            *(float4*)&C[r * 96 + c0] = o;
            if (DUP) *(float4*)&C2[r * 96 + c0] = o;
        }
    }
}

// ---------------- per-node attention scores ----------------
__global__ void scores_k(const float* __restrict__ hp,
                         const float* __restrict__ as_, const float* __restrict__ ad_,
                         float* __restrict__ ss, float* __restrict__ sd)
{
    int w = (blockIdx.x * blockDim.x + threadIdx.x) >> 5;
    int lane = threadIdx.x & 31;
    if (w >= Nn) return;
    const float* row = hp + w * 96;
    float s1 = 0.f, s2 = 0.f;
    #pragma unroll
    for (int j = 0; j < 3; j++) {
        float v = row[lane + 32 * j];
        s1 = fmaf(v, as_[lane + 32 * j], s1);
        s2 = fmaf(v, ad_[lane + 32 * j], s2);
    }
    #pragma unroll
    for (int o = 16; o; o >>= 1) {
        s1 += __shfl_xor_sync(0xffffffffu, s1, o);
        s2 += __shfl_xor_sync(0xffffffffu, s2, o);
    }
    if (lane == 0) { ss[w] = s1; sd[w] = s2; }
}

// ---------------- GAT aggregation (warp/dst) + ATOMIC-FREE fused BN stats ----
// max-free softmax (scores are bounded: BN'd activations x small weights).
// 512 threads = 16 warps/block; per-warp channel partials via plain STS,
// one block reduction, 192 global RED.ADDs per block.
__global__ __launch_bounds__(512) void agg_k(
    const float* __restrict__ hp,
    const float* __restrict__ ss, const float* __restrict__ sd,
    const float* __restrict__ bias, float* __restrict__ out,
    float* __restrict__ sumP, float* __restrict__ sqP)
{
    __shared__ float bw0[16][96];
    __shared__ float bw1[16][96];
    int tid = threadIdx.x;
    int warp = tid >> 5, lane = tid & 31;
    int d = (blockIdx.x * blockDim.x + tid) >> 5;
    float v0 = 0.f, v1 = 0.f, v2 = 0.f;
    if (d < Nn) {
        int s0 = g_rs[d], s1e = g_rs[d + 1];
        float sdd = sd[d];
        // pass 1: denominator + cache numerators
        float denom = 0.f;
        for (int j = s0 + lane; j < s1e; j += 32) {
            int s = g_csr[j];
            float e = ss[s] + sdd;
            e = (e >= 0.f) ? e : 0.2f * e;
            float wv = __expf(e);
            g_ew[j] = wv;
            denom += wv;
        }
        #pragma unroll
        for (int o = 16; o; o >>= 1) denom += __shfl_xor_sync(0xffffffffu, denom, o);
        float inv = 1.f / denom;
        // pass 2: weighted feature aggregation
        float a0 = 0.f, a1 = 0.f, a2 = 0.f;
        for (int j = s0; j < s1e; j++) {
            int s = g_csr[j];               // warp-uniform broadcast
            float wgt = g_ew[j] * inv;
            const float* row = hp + s * 96;
            a0 = fmaf(wgt, row[lane], a0);
            a1 = fmaf(wgt, row[lane + 32], a1);
            a2 = fmaf(wgt, row[lane + 64], a2);
        }
        v0 = a0 + bias[lane];
        v1 = a1 + bias[lane + 32];
        v2 = a2 + bias[lane + 64];
        out[d * 96 + lane]      = v0;
        out[d * 96 + lane + 32] = v1;
        out[d * 96 + lane + 64] = v2;
    }
    // per-warp channel partials (plain stores, lane == channel owner)
    bw0[warp][lane]      = v0;       bw1[warp][lane]      = v0 * v0;
    bw0[warp][lane + 32] = v1;       bw1[warp][lane + 32] = v1 * v1;
    bw0[warp][lane + 64] = v2;       bw1[warp][lane + 64] = v2 * v2;
    __syncthreads();
    if (tid < 96) {
        float s = 0.f, q = 0.f;
        #pragma unroll
        for (int w = 0; w < 16; w++) { s += bw0[w][tid]; q += bw1[w][tid]; }
        atomicAdd(&sumP[tid], s);
        atomicAdd(&sqP[tid], q);
    }
}

// ---------------- fused BN-apply + Poincare expmap0 + segment pooling ----------------
__global__ void expool_k(const float* __restrict__ t, const float* __restrict__ idn,
                         const float* __restrict__ gma, const float* __restrict__ bta,
                         const float* __restrict__ sumP, const float* __restrict__ sqP,
                         const int* __restrict__ batch)
{
    __shared__ float sp[Gg * Hh];
    __shared__ float scn[Gg];
    __shared__ float s_sc[96], s_sh[96];
    if (threadIdx.x < 96) {
        int c = threadIdx.x;
        float mu = sumP[c] * (1.f / Nn);
        float var = sqP[c] * (1.f / Nn) - mu * mu;
        float is = rsqrtf(var + BNEPS);
        float gv = gma[c];
        s_sc[c] = gv * is;
        s_sh[c] = bta[c] - mu * gv * is;
    }
    for (int i = threadIdx.x; i < Gg * Hh; i += blockDim.x) sp[i] = 0.f;
    if (threadIdx.x < Gg) scn[threadIdx.x] = 0.f;
    __syncthreads();
    int lane = threadIdx.x & 31;
    int warp = (blockIdx.x * blockDim.x + threadIdx.x) >> 5;
    int nwarps = (gridDim.x * blockDim.x) >> 5;
    for (int n = warp; n < Nn; n += nwarps) {
        float v0 = lrelu01(fmaf(t[n * 96 + lane],      s_sc[lane],      s_sh[lane]))      + idn[n * 96 + lane];
        float v1 = lrelu01(fmaf(t[n * 96 + lane + 32], s_sc[lane + 32], s_sh[lane + 32])) + idn[n * 96 + lane + 32];
        float v2 = lrelu01(fmaf(t[n * 96 + lane + 64], s_sc[lane + 64], s_sh[lane + 64])) + idn[n * 96 + lane + 64];
        float q = v0 * v0 + v1 * v1 + v2 * v2;
        #pragma unroll
        for (int o = 16; o; o >>= 1) q += __shfl_xor_sync(0xffffffffu, q, o);
        float nrm = fmaxf(sqrtf(q), 1e-15f);
        float s = tanhf(nrm) / nrm;
        int g = batch[n];
        atomicAdd(&sp[g * 96 + lane], v0 * s);
        atomicAdd(&sp[g * 96 + lane + 32], v1 * s);
        atomicAdd(&sp[g * 96 + lane + 64], v2 * s);
        if (lane == 0) atomicAdd(&scn[g], 1.f);
    }
    __syncthreads();
    for (int i = threadIdx.x; i < Gg * Hh; i += blockDim.x) atomicAdd(&g_pooled[i], sp[i]);
    if (threadIdx.x < Gg) atomicAdd(&g_cnt[threadIdx.x], scn[threadIdx.x]);
}

// ---------------- head ----------------
__global__ void head_k(const float* __restrict__ fc3W, const float* __restrict__ fc3b,
                       const float* __restrict__ fc4W, const float* __restrict__ fc4b,
                       float* __restrict__ out)
{
    __shared__ float p[Gg * Hh];
    __shared__ float o1[Gg * 48];
    for (int i = threadIdx.x; i < Gg * Hh; i += blockDim.x) {
        int g = i / 96;
        p[i] = g_pooled[i] / fmaxf(g_cnt[g], 1.f);
    }
    __syncthreads();
    for (int i = threadIdx.x; i < Gg * 48; i += blockDim.x) {
        int g = i / 48, c = i % 48;
        float a = fc3b[c];
        for (int k = 0; k < 96; k++) a = fmaf(p[g * 96 + k], fc3W[k * 48 + c], a);
        o1[i] = lrelu01(a);
    }
    __syncthreads();
    for (int i = threadIdx.x; i < Gg * NCLS; i += blockDim.x) {
        int g = i / NCLS, c = i % NCLS;
        float a = fc4b[c];
        for (int k = 0; k < 48; k++) a = fmaf(o1[g * 48 + k], fc4W[k * NCLS + c], a);
        out[i] = a;
    }
}

// ---------------- launch ----------------
extern "C" void kernel_launch(void* const* d_in, const int* in_sizes, int n_in,
                              void* d_out, int out_size)
{
    const float* x     = (const float*)d_in[0];
    const int*   ei    = (const int*)d_in[1];
    const int*   batch = (const int*)d_in[2];
    const float* embW  = (const float*)d_in[3];
    const float* embB  = (const float*)d_in[4];
    const float* cW[3]  = {(const float*)d_in[5],  (const float*)d_in[9],  (const float*)d_in[13]};
    const float* cAS[3] = {(const float*)d_in[6],  (const float*)d_in[10], (const float*)d_in[14]};
    const float* cAD[3] = {(const float*)d_in[7],  (const float*)d_in[11], (const float*)d_in[15]};
    const float* cB[3]  = {(const float*)d_in[8],  (const float*)d_in[12], (const float*)d_in[16]};
    const float* fcW[2] = {(const float*)d_in[17], (const float*)d_in[19]};
    const float* fcB[2] = {(const float*)d_in[18], (const float*)d_in[20]};
    const float* bnG[3] = {(const float*)d_in[21], (const float*)d_in[23], (const float*)d_in[25]};
    const float* bnB[3] = {(const float*)d_in[22], (const float*)d_in[24], (const float*)d_in[26]};
    const float* fc3W = (const float*)d_in[27];
    const float* fc3b = (const float*)d_in[28];
    const float* fc4W = (const float*)d_in[29];
    const float* fc4b = (const float*)d_in[30];
    float* out = (float*)d_out;

    float *ph, *pid, *php, *ptmp, *pss, *psd, *pbs, *pbq;
    cudaGetSymbolAddress((void**)&ph,   g_h);
    cudaGetSymbolAddress((void**)&pid,  g_id);
    cudaGetSymbolAddress((void**)&php,  g_hp);
    cudaGetSymbolAddress((void**)&ptmp, g_tmp);
    cudaGetSymbolAddress((void**)&pss,  g_ss);
    cudaGetSymbolAddress((void**)&psd,  g_sd);
    cudaGetSymbolAddress((void**)&pbs,  g_bnsum);
    cudaGetSymbolAddress((void**)&pbq,  g_bnsq);

    const int EB = (ETOT + 255) / 256;
    const int GB = (Nn + 127) / 128;
    const int WB = (Nn * 32 + 255) / 256;      // scores_k: warp per node, 256 thd
    const int AB = (Nn * 32 + 511) / 512;      // agg_k: warp per node, 512 thd

    // Fork: CSR build concurrent with embed GEMM. Streams/events intentionally
    // leaked (destroying them mid-capture would abort graph capture).
    cudaStream_t s1;
    cudaStreamCreateWithFlags(&s1, cudaStreamNonBlocking);
    cudaEvent_t evFork, evJoin;
    cudaEventCreateWithFlags(&evFork, cudaEventDisableTiming);
    cudaEventCreateWithFlags(&evJoin, cudaEventDisableTiming);

    cudaEventRecord(evFork, 0);
    cudaStreamWaitEvent(s1, evFork, 0);
    zero_k<<<256, 256, 0, s1>>>();
    count_k<<<EB, 256, 0, s1>>>(ei);
    scan_k<<<1, 1024, 0, s1>>>();
    scatter_k<<<EB, 256, 0, s1>>>(ei);
    cudaEventRecord(evJoin, s1);

    // embed: h = lrelu(x @ embW + embB); identity = h
    gemm128<1, 0, 1><<<GB, 384>>>(x, nullptr, nullptr, nullptr, nullptr, nullptr,
                                  embW, embB, ph, pid, Nn, 256);

    for (int l = 0; l < 3; l++) {
        // hp = h @ cW
        gemm128<0, 0, 0><<<GB, 384>>>(ph, nullptr, nullptr, nullptr, nullptr, nullptr,
                                      cW[l], nullptr, php, nullptr, Nn, 96);
        scores_k<<<WB, 256>>>(php, cAS[l], cAD[l], pss, psd);
        if (l == 0) cudaStreamWaitEvent(0, evJoin, 0);   // CSR + zeroed BN slots ready
        agg_k<<<AB, 512>>>(php, pss, psd, cB[l], ptmp, pbs + l * Hh, pbq + l * Hh);
        if (l < 2) {
            // h = lrelu( (lrelu(bn(tmp)) + id) @ fcW + fcB ) — BN fused into A-load
            gemm128<1, 1, 0><<<GB, 384>>>(ptmp, pid, bnG[l], bnB[l], pbs + l * Hh, pbq + l * Hh,
                                          fcW[l], fcB[l], ph, nullptr, Nn, 96);
        }
    }

    expool_k<<<160, 256>>>(ptmp, pid, bnG[2], bnB[2], pbs + 2 * Hh, pbq + 2 * Hh, batch);
    head_k<<<1, 256>>>(fc3W, fc3b, fc4W, fc4b, out);
}

// round 10
// speedup vs baseline: 1.1829x; 1.0027x over previous
#include <cuda_runtime.h>
#include <math.h>

#define Nn 50000
#define Ee 800000
#define ETOT 850000
#define Hh 96
#define Gg 64
#define NCLS 4
#define BNEPS 1e-5f

// ---------------- device scratch ----------------
__device__ float g_h[Nn * Hh];
__device__ float g_id[Nn * Hh];
__device__ float g_hp[Nn * Hh];
__device__ float g_tmp[Nn * Hh];
__device__ float g_ss[Nn], g_sd[Nn];
__device__ float g_ew[ETOT];
__device__ int   g_deg[Nn];
__device__ int   g_rs[Nn + 1];
__device__ int   g_cur[Nn];
__device__ int   g_csr[ETOT];
__device__ float g_bnsum[3 * Hh], g_bnsq[3 * Hh];
__device__ float g_pooled[Gg * Hh];
__device__ float g_cnt[Gg];

__device__ __forceinline__ float lrelu01(float v) { return v >= 0.f ? v : 0.01f * v; }

// ---------------- zero / init ----------------
__global__ void zero_k() {
    int i = blockIdx.x * blockDim.x + threadIdx.x;
    int stride = gridDim.x * blockDim.x;
    for (int j = i; j < Nn; j += stride) g_deg[j] = 0;
    if (i < Gg * Hh) g_pooled[i] = 0.f;
    if (i < Gg) g_cnt[i] = 0.f;
    if (i < 3 * Hh) { g_bnsum[i] = 0.f; g_bnsq[i] = 0.f; }
}

// ---------------- CSR build ----------------
__global__ void count_k(const int* __restrict__ ei) {
    int i = blockIdx.x * blockDim.x + threadIdx.x;
    if (i >= ETOT) return;
    int d = (i < Ee) ? ei[Ee + i] : (i - Ee);
    atomicAdd(&g_deg[d], 1);
}

__global__ void scan_k() {
    __shared__ int part[1024];
    int t = threadIdx.x;
    const int CH = (Nn + 1023) / 1024;
    int base = t * CH;
    int s = 0;
    for (int i = 0; i < CH; i++) {
        int idx = base + i;
        if (idx < Nn) s += g_deg[idx];
    }
    part[t] = s;
    __syncthreads();
    for (int off = 1; off < 1024; off <<= 1) {
        int v = (t >= off) ? part[t - off] : 0;
        __syncthreads();
        part[t] += v;
        __syncthreads();
    }
    int run = (t == 0) ? 0 : part[t - 1];
    for (int i = 0; i < CH; i++) {
        int idx = base + i;
        if (idx < Nn) {
            g_rs[idx] = run;
            g_cur[idx] = run;
            run += g_deg[idx];
        }
    }
    if (t == blockDim.x - 1) g_rs[Nn] = part[blockDim.x - 1];
}

__global__ void scatter_k(const int* __restrict__ ei) {
    int i = blockIdx.x * blockDim.x + threadIdx.x;
    if (i >= ETOT) return;
    int sN, dN;
    if (i < Ee) { sN = ei[i]; dN = ei[Ee + i]; }
    else        { sN = i - Ee; dN = i - Ee; }
    int pos = atomicAdd(&g_cur[dN], 1);
    g_csr[pos] = sN;
}

// ---------------- GEMM: C[M,96] = act(A'[M,K] @ W[K,96] + bias) ----------------
// tile 128x96, 384 threads, micro-tile 8x4 (plain FFMA — proven core).
// MODE==1: A' = lrelu(bn(A)) + A2 fused on A-load (K must be 96).
// SCORES==1: emit per-row ss/sd via atomic-free smem partial reduction
//            (reuses the Ash/Wsh smem region, dead after the main loop).
template <int ACT, int MODE, int DUP, int SCORES>
__global__ __launch_bounds__(384, 2) void gemm128(
    const float* __restrict__ A, const float* __restrict__ A2,
    const float* __restrict__ gma, const float* __restrict__ bta,
    const float* __restrict__ sumP, const float* __restrict__ sqP,
    const float* __restrict__ W, const float* __restrict__ bias,
    const float* __restrict__ as_, const float* __restrict__ ad_,
    float* __restrict__ ssO, float* __restrict__ sdO,
    float* __restrict__ C, float* __restrict__ C2, int M, int K)
{
    __shared__ __align__(16) char sbuf[16896 + 12288];   // Ash | Wsh ; reused as sSD
    float (*Ash)[132] = (float (*)[132])sbuf;            // [32][132]
    float (*Wsh)[96]  = (float (*)[96])(sbuf + 16896);   // [32][96]
    float2 (*sSD)[25] = (float2 (*)[25])sbuf;            // [128][25] = 25.6KB <= 29.2KB
    __shared__ float s_sc[96], s_sh[96];
    int tid = threadIdx.x;
    if (MODE == 1) {
        if (tid < 96) {
            float mu = sumP[tid] * (1.f / Nn);
            float var = sqP[tid] * (1.f / Nn) - mu * mu;
            float is = rsqrtf(var + BNEPS);
            float gv = gma[tid];
            s_sc[tid] = gv * is;
            s_sh[tid] = bta[tid] - mu * gv * is;
        }
        __syncthreads();
    }
    int cg = tid % 24;               // cols cg*4..+3
    int rg = tid / 24;               // rows rg*8..+7
    int rowBase = blockIdx.x * 128;
    float acc[8][4] = {};
    for (int kc = 0; kc < K; kc += 32) {
        for (int idx = tid; idx < 1024; idx += 384) {
            int m = idx >> 3, kq = idx & 7;
            int r = rowBase + m;
            float4 v = make_float4(0.f, 0.f, 0.f, 0.f);
            if (r < M) {
                v = *(const float4*)&A[r * K + kc + kq * 4];
                if (MODE == 1) {
                    float4 u = *(const float4*)&A2[r * K + kc + kq * 4];
                    int c = kc + kq * 4;
                    v.x = lrelu01(fmaf(v.x, s_sc[c + 0], s_sh[c + 0])) + u.x;
                    v.y = lrelu01(fmaf(v.y, s_sc[c + 1], s_sh[c + 1])) + u.y;
                    v.z = lrelu01(fmaf(v.z, s_sc[c + 2], s_sh[c + 2])) + u.z;
                    v.w = lrelu01(fmaf(v.w, s_sc[c + 3], s_sh[c + 3])) + u.w;
                }
            }
            int k0 = kq * 4;
            Ash[k0 + 0][m] = v.x;
            Ash[k0 + 1][m] = v.y;
            Ash[k0 + 2][m] = v.z;
            Ash[k0 + 3][m] = v.w;
        }
        #pragma unroll
        for (int j = 0; j < 8; j++) {
            int idx = tid + j * 384;
            int k = idx / 96, c = idx % 96;
            Wsh[k][c] = W[(kc + k) * 96 + c];
        }
        __syncthreads();
        #pragma unroll
        for (int k = 0; k < 32; k++) {
            float4 al = *(const float4*)&Ash[k][rg * 8];
            float4 ah = *(const float4*)&Ash[k][rg * 8 + 4];
            float4 w  = *(const float4*)&Wsh[k][cg * 4];
            float av[8] = {al.x, al.y, al.z, al.w, ah.x, ah.y, ah.z, ah.w};
            float wv[4] = {w.x, w.y, w.z, w.w};
            #pragma unroll
            for (int i = 0; i < 8; i++)
                #pragma unroll
                for (int j = 0; j < 4; j++)
                    acc[i][j] = fmaf(av[i], wv[j], acc[i][j]);
        }
        __syncthreads();
    }
    int c0 = cg * 4;
    float bv[4];
    #pragma unroll
    for (int j = 0; j < 4; j++) bv[j] = bias ? bias[c0 + j] : 0.f;
    float asv[4], adv[4];
    if (SCORES) {
        #pragma unroll
        for (int j = 0; j < 4; j++) { asv[j] = as_[c0 + j]; adv[j] = ad_[c0 + j]; }
    }
    int r0 = rowBase + rg * 8;
    #pragma unroll
    for (int i = 0; i < 8; i++) {
        int r = r0 + i;
        if (SCORES) {
            float s1 = acc[i][0] * asv[0] + acc[i][1] * asv[1] + acc[i][2] * asv[2] + acc[i][3] * asv[3];
            float s2 = acc[i][0] * adv[0] + acc[i][1] * adv[1] + acc[i][2] * adv[2] + acc[i][3] * adv[3];
            sSD[rg * 8 + i][cg] = make_float2(s1, s2);   // plain STS, no collisions
        }
        if (r < M) {
            float v0 = acc[i][0] + bv[0];
            float v1 = acc[i][1] + bv[1];
            float v2 = acc[i][2] + bv[2];
            float v3 = acc[i][3] + bv[3];
            if (ACT) { v0 = lrelu01(v0); v1 = lrelu01(v1); v2 = lrelu01(v2); v3 = lrelu01(v3); }
            float4 o = make_float4(v0, v1, v2, v3);
            *(float4*)&C[r * 96 + c0] = o;
            if (DUP) *(float4*)&C2[r * 96 + c0] = o;
        }
    }
    if (SCORES) {
        __syncthreads();
        if (tid < 128) {
            float s1 = 0.f, s2 = 0.f;
            #pragma unroll
            for (int c = 0; c < 24; c++) {
                float2 v = sSD[tid][c];
                s1 += v.x; s2 += v.y;
            }
            int r = rowBase + tid;
            if (r < M) { ssO[r] = s1; sdO[r] = s2; }
        }
    }
}

// ---------------- GAT aggregation (warp/dst) + atomic-free fused BN stats ----
// max-free softmax (scores are bounded: BN'd activations x small weights).
__global__ __launch_bounds__(512) void agg_k(
    const float* __restrict__ hp,
    const float* __restrict__ ss, const float* __restrict__ sd,
    const float* __restrict__ bias, float* __restrict__ out,
    float* __restrict__ sumP, float* __restrict__ sqP)
{
    __shared__ float bw0[16][96];
    __shared__ float bw1[16][96];
    int tid = threadIdx.x;
    int warp = tid >> 5, lane = tid & 31;
    int d = (blockIdx.x * blockDim.x + tid) >> 5;
    float v0 = 0.f, v1 = 0.f, v2 = 0.f;
    if (d < Nn) {
        int s0 = g_rs[d], s1e = g_rs[d + 1];
        float sdd = sd[d];
        float denom = 0.f;
        for (int j = s0 + lane; j < s1e; j += 32) {
            int s = g_csr[j];
            float e = ss[s] + sdd;
            e = (e >= 0.f) ? e : 0.2f * e;
            float wv = __expf(e);
            g_ew[j] = wv;
            denom += wv;
        }
        #pragma unroll
        for (int o = 16; o; o >>= 1) denom += __shfl_xor_sync(0xffffffffu, denom, o);
        float inv = 1.f / denom;
        float a0 = 0.f, a1 = 0.f, a2 = 0.f;
        for (int j = s0; j < s1e; j++) {
            int s = g_csr[j];               // warp-uniform broadcast
            float wgt = g_ew[j] * inv;
            const float* row = hp + s * 96;
            a0 = fmaf(wgt, row[lane], a0);
            a1 = fmaf(wgt, row[lane + 32], a1);
            a2 = fmaf(wgt, row[lane + 64], a2);
        }
        v0 = a0 + bias[lane];
        v1 = a1 + bias[lane + 32];
        v2 = a2 + bias[lane + 64];
        out[d * 96 + lane]      = v0;
        out[d * 96 + lane + 32] = v1;
        out[d * 96 + lane + 64] = v2;
    }
    bw0[warp][lane]      = v0;       bw1[warp][lane]      = v0 * v0;
    bw0[warp][lane + 32] = v1;       bw1[warp][lane + 32] = v1 * v1;
    bw0[warp][lane + 64] = v2;       bw1[warp][lane + 64] = v2 * v2;
    __syncthreads();
    if (tid < 96) {
        float s = 0.f, q = 0.f;
        #pragma unroll
        for (int w = 0; w < 16; w++) { s += bw0[w][tid]; q += bw1[w][tid]; }
        atomicAdd(&sumP[tid], s);
        atomicAdd(&sqP[tid], q);
    }
}

// ---------------- fused BN-apply + Poincare expmap0 + segment pooling ----------------
__global__ void expool_k(const float* __restrict__ t, const float* __restrict__ idn,
                         const float* __restrict__ gma, const float* __restrict__ bta,
                         const float* __restrict__ sumP, const float* __restrict__ sqP,
                         const int* __restrict__ batch)
{
    __shared__ float sp[Gg * Hh];
    __shared__ float scn[Gg];
    __shared__ float s_sc[96], s_sh[96];
    if (threadIdx.x < 96) {
        int c = threadIdx.x;
        float mu = sumP[c] * (1.f / Nn);
        float var = sqP[c] * (1.f / Nn) - mu * mu;
        float is = rsqrtf(var + BNEPS);
        float gv = gma[c];
        s_sc[c] = gv * is;
        s_sh[c] = bta[c] - mu * gv * is;
    }
    for (int i = threadIdx.x; i < Gg * Hh; i += blockDim.x) sp[i] = 0.f;
    if (threadIdx.x < Gg) scn[threadIdx.x] = 0.f;
    __syncthreads();
    int lane = threadIdx.x & 31;
    int warp = (blockIdx.x * blockDim.x + threadIdx.x) >> 5;
    int nwarps = (gridDim.x * blockDim.x) >> 5;
    for (int n = warp; n < Nn; n += nwarps) {
        float v0 = lrelu01(fmaf(t[n * 96 + lane],      s_sc[lane],      s_sh[lane]))      + idn[n * 96 + lane];
        float v1 = lrelu01(fmaf(t[n * 96 + lane + 32], s_sc[lane + 32], s_sh[lane + 32])) + idn[n * 96 + lane + 32];
        float v2 = lrelu01(fmaf(t[n * 96 + lane + 64], s_sc[lane + 64], s_sh[lane + 64])) + idn[n * 96 + lane + 64];
        float q = v0 * v0 + v1 * v1 + v2 * v2;
        #pragma unroll
        for (int o = 16; o; o >>= 1) q += __shfl_xor_sync(0xffffffffu, q, o);
        float nrm = fmaxf(sqrtf(q), 1e-15f);
        float s = tanhf(nrm) / nrm;
        int g = batch[n];
        atomicAdd(&sp[g * 96 + lane], v0 * s);
        atomicAdd(&sp[g * 96 + lane + 32], v1 * s);
        atomicAdd(&sp[g * 96 + lane + 64], v2 * s);
        if (lane == 0) atomicAdd(&scn[g], 1.f);
    }
    __syncthreads();
    for (int i = threadIdx.x; i < Gg * Hh; i += blockDim.x) atomicAdd(&g_pooled[i], sp[i]);
    if (threadIdx.x < Gg) atomicAdd(&g_cnt[threadIdx.x], scn[threadIdx.x]);
}

// ---------------- head ----------------
__global__ void head_k(const float* __restrict__ fc3W, const float* __restrict__ fc3b,
                       const float* __restrict__ fc4W, const float* __restrict__ fc4b,
                       float* __restrict__ out)
{
    __shared__ float p[Gg * Hh];
    __shared__ float o1[Gg * 48];
    for (int i = threadIdx.x; i < Gg * Hh; i += blockDim.x) {
        int g = i / 96;
        p[i] = g_pooled[i] / fmaxf(g_cnt[g], 1.f);
    }
    __syncthreads();
    for (int i = threadIdx.x; i < Gg * 48; i += blockDim.x) {
        int g = i / 48, c = i % 48;
        float a = fc3b[c];
        for (int k = 0; k < 96; k++) a = fmaf(p[g * 96 + k], fc3W[k * 48 + c], a);
        o1[i] = lrelu01(a);
    }
    __syncthreads();
    for (int i = threadIdx.x; i < Gg * NCLS; i += blockDim.x) {
        int g = i / NCLS, c = i % NCLS;
        float a = fc4b[c];
        for (int k = 0; k < 48; k++) a = fmaf(o1[g * 48 + k], fc4W[k * NCLS + c], a);
        out[i] = a;
    }
}

// ---------------- launch ----------------
extern "C" void kernel_launch(void* const* d_in, const int* in_sizes, int n_in,
                              void* d_out, int out_size)
{
    const float* x     = (const float*)d_in[0];
    const int*   ei    = (const int*)d_in[1];
    const int*   batch = (const int*)d_in[2];
    const float* embW  = (const float*)d_in[3];
    const float* embB  = (const float*)d_in[4];
    const float* cW[3]  = {(const float*)d_in[5],  (const float*)d_in[9],  (const float*)d_in[13]};
    const float* cAS[3] = {(const float*)d_in[6],  (const float*)d_in[10], (const float*)d_in[14]};
    const float* cAD[3] = {(const float*)d_in[7],  (const float*)d_in[11], (const float*)d_in[15]};
    const float* cB[3]  = {(const float*)d_in[8],  (const float*)d_in[12], (const float*)d_in[16]};
    const float* fcW[2] = {(const float*)d_in[17], (const float*)d_in[19]};
    const float* fcB[2] = {(const float*)d_in[18], (const float*)d_in[20]};
    const float* bnG[3] = {(const float*)d_in[21], (const float*)d_in[23], (const float*)d_in[25]};
    const float* bnB[3] = {(const float*)d_in[22], (const float*)d_in[24], (const float*)d_in[26]};
    const float* fc3W = (const float*)d_in[27];
    const float* fc3b = (const float*)d_in[28];
    const float* fc4W = (const float*)d_in[29];
    const float* fc4b = (const float*)d_in[30];
    float* out = (float*)d_out;

    float *ph, *pid, *php, *ptmp, *pss, *psd, *pbs, *pbq;
    cudaGetSymbolAddress((void**)&ph,   g_h);
    cudaGetSymbolAddress((void**)&pid,  g_id);
    cudaGetSymbolAddress((void**)&php,  g_hp);
    cudaGetSymbolAddress((void**)&ptmp, g_tmp);
    cudaGetSymbolAddress((void**)&pss,  g_ss);
    cudaGetSymbolAddress((void**)&psd,  g_sd);
    cudaGetSymbolAddress((void**)&pbs,  g_bnsum);
    cudaGetSymbolAddress((void**)&pbq,  g_bnsq);

    const int EB = (ETOT + 255) / 256;
    const int GB = (Nn + 127) / 128;
    const int AB = (Nn * 32 + 511) / 512;

    // Fork: CSR build concurrent with embed GEMM. Streams/events intentionally
    // leaked (destroying them mid-capture would abort graph capture).
    cudaStream_t s1;
    cudaStreamCreateWithFlags(&s1, cudaStreamNonBlocking);
    cudaEvent_t evFork, evJoin;
    cudaEventCreateWithFlags(&evFork, cudaEventDisableTiming);
    cudaEventCreateWithFlags(&evJoin, cudaEventDisableTiming);

    cudaEventRecord(evFork, 0);
    cudaStreamWaitEvent(s1, evFork, 0);
    zero_k<<<256, 256, 0, s1>>>();
    count_k<<<EB, 256, 0, s1>>>(ei);
    scan_k<<<1, 1024, 0, s1>>>();
    scatter_k<<<EB, 256, 0, s1>>>(ei);
    cudaEventRecord(evJoin, s1);

    // embed: h = lrelu(x @ embW + embB); identity = h
    gemm128<1, 0, 1, 0><<<GB, 384>>>(x, nullptr, nullptr, nullptr, nullptr, nullptr,
                                     embW, embB, nullptr, nullptr, nullptr, nullptr,
                                     ph, pid, Nn, 256);

    for (int l = 0; l < 3; l++) {
        // hp = h @ cW  (+ fused atomic-free attention scores)
        gemm128<0, 0, 0, 1><<<GB, 384>>>(ph, nullptr, nullptr, nullptr, nullptr, nullptr,
                                         cW[l], nullptr, cAS[l], cAD[l], pss, psd,
                                         php, nullptr, Nn, 96);
        if (l == 0) cudaStreamWaitEvent(0, evJoin, 0);   // CSR + zeroed BN slots ready
        agg_k<<<AB, 512>>>(php, pss, psd, cB[l], ptmp, pbs + l * Hh, pbq + l * Hh);
        if (l < 2) {
            // h = lrelu( (lrelu(bn(tmp)) + id) @ fcW + fcB ) — BN fused into A-load
            gemm128<1, 1, 0, 0><<<GB, 384>>>(ptmp, pid, bnG[l], bnB[l], pbs + l * Hh, pbq + l * Hh,
                                             fcW[l], fcB[l], nullptr, nullptr, nullptr, nullptr,
                                             ph, nullptr, Nn, 96);
        }
    }

    expool_k<<<160, 256>>>(ptmp, pid, bnG[2], bnB[2], pbs + 2 * Hh, pbq + 2 * Hh, batch);
    head_k<<<1, 256>>>(fc3W, fc3b, fc4W, fc4b, out);
}

// round 11
// speedup vs baseline: 1.2047x; 1.0184x over previous
#include <cuda_runtime.h>
#include <math.h>

#define Nn 50000
#define Ee 800000
#define ETOT 850000
#define Hh 96
#define Gg 64
#define NCLS 4
#define BNEPS 1e-5f

// ---------------- device scratch ----------------
__device__ float g_h[Nn * Hh];
__device__ float g_id[Nn * Hh];
__device__ float g_hp[Nn * Hh];
__device__ float g_tmp[Nn * Hh];
__device__ float g_ss[Nn], g_sd[Nn];
__device__ int   g_deg[Nn];
__device__ int   g_rs[Nn + 1];
__device__ int   g_cur[Nn];
__device__ int   g_csr[ETOT];
__device__ float g_bnsum[3 * Hh], g_bnsq[3 * Hh];
__device__ float g_pooled[Gg * Hh];
__device__ float g_cnt[Gg];

__device__ __forceinline__ float lrelu01(float v) { return v >= 0.f ? v : 0.01f * v; }

// ---------------- zero / init ----------------
__global__ void zero_k() {
    int i = blockIdx.x * blockDim.x + threadIdx.x;
    int stride = gridDim.x * blockDim.x;
    for (int j = i; j < Nn; j += stride) g_deg[j] = 0;
    if (i < Gg * Hh) g_pooled[i] = 0.f;
    if (i < Gg) g_cnt[i] = 0.f;
    if (i < 3 * Hh) { g_bnsum[i] = 0.f; g_bnsq[i] = 0.f; }
}

// ---------------- CSR build ----------------
__global__ void count_k(const int* __restrict__ ei) {
    int i = blockIdx.x * blockDim.x + threadIdx.x;
    if (i >= ETOT) return;
    int d = (i < Ee) ? ei[Ee + i] : (i - Ee);
    atomicAdd(&g_deg[d], 1);
}

__global__ void scan_k() {
    __shared__ int part[1024];
    int t = threadIdx.x;
    const int CH = (Nn + 1023) / 1024;
    int base = t * CH;
    int s = 0;
    for (int i = 0; i < CH; i++) {
        int idx = base + i;
        if (idx < Nn) s += g_deg[idx];
    }
    part[t] = s;
    __syncthreads();
    for (int off = 1; off < 1024; off <<= 1) {
        int v = (t >= off) ? part[t - off] : 0;
        __syncthreads();
        part[t] += v;
        __syncthreads();
    }
    int run = (t == 0) ? 0 : part[t - 1];
    for (int i = 0; i < CH; i++) {
        int idx = base + i;
        if (idx < Nn) {
            g_rs[idx] = run;
            g_cur[idx] = run;
            run += g_deg[idx];
        }
    }
    if (t == blockDim.x - 1) g_rs[Nn] = part[blockDim.x - 1];
}

__global__ void scatter_k(const int* __restrict__ ei) {
    int i = blockIdx.x * blockDim.x + threadIdx.x;
    if (i >= ETOT) return;
    int sN, dN;
    if (i < Ee) { sN = ei[i]; dN = ei[Ee + i]; }
    else        { sN = i - Ee; dN = i - Ee; }
    int pos = atomicAdd(&g_cur[dN], 1);
    g_csr[pos] = sN;
}

// ---------------- GEMM: C[M,96] = act(A'[M,K] @ W[K,96] + bias) ----------------
// tile 128x96, 384 threads, micro-tile 8x4 (plain FFMA — proven core).
// MODE==1: A' = lrelu(bn(A)) + A2 fused on A-load (K must be 96).
// SCORES==1: emit per-row ss/sd via atomic-free smem partial reduction.
template <int ACT, int MODE, int DUP, int SCORES>
__global__ __launch_bounds__(384, 2) void gemm128(
    const float* __restrict__ A, const float* __restrict__ A2,
    const float* __restrict__ gma, const float* __restrict__ bta,
    const float* __restrict__ sumP, const float* __restrict__ sqP,
    const float* __restrict__ W, const float* __restrict__ bias,
    const float* __restrict__ as_, const float* __restrict__ ad_,
    float* __restrict__ ssO, float* __restrict__ sdO,
    float* __restrict__ C, float* __restrict__ C2, int M, int K)
{
    __shared__ __align__(16) char sbuf[16896 + 12288];   // Ash | Wsh ; reused as sSD
    float (*Ash)[132] = (float (*)[132])sbuf;            // [32][132]
    float (*Wsh)[96]  = (float (*)[96])(sbuf + 16896);   // [32][96]
    float2 (*sSD)[25] = (float2 (*)[25])sbuf;            // [128][25]
    __shared__ float s_sc[96], s_sh[96];
    int tid = threadIdx.x;
    if (MODE == 1) {
        if (tid < 96) {
            float mu = sumP[tid] * (1.f / Nn);
            float var = sqP[tid] * (1.f / Nn) - mu * mu;
            float is = rsqrtf(var + BNEPS);
            float gv = gma[tid];
            s_sc[tid] = gv * is;
            s_sh[tid] = bta[tid] - mu * gv * is;
        }
        __syncthreads();
    }
    int cg = tid % 24;               // cols cg*4..+3
    int rg = tid / 24;               // rows rg*8..+7
    int rowBase = blockIdx.x * 128;
    float acc[8][4] = {};
    for (int kc = 0; kc < K; kc += 32) {
        for (int idx = tid; idx < 1024; idx += 384) {
            int m = idx >> 3, kq = idx & 7;
            int r = rowBase + m;
            float4 v = make_float4(0.f, 0.f, 0.f, 0.f);
            if (r < M) {
                v = *(const float4*)&A[r * K + kc + kq * 4];
                if (MODE == 1) {
                    float4 u = *(const float4*)&A2[r * K + kc + kq * 4];
                    int c = kc + kq * 4;
                    v.x = lrelu01(fmaf(v.x, s_sc[c + 0], s_sh[c + 0])) + u.x;
                    v.y = lrelu01(fmaf(v.y, s_sc[c + 1], s_sh[c + 1])) + u.y;
                    v.z = lrelu01(fmaf(v.z, s_sc[c + 2], s_sh[c + 2])) + u.z;
                    v.w = lrelu01(fmaf(v.w, s_sc[c + 3], s_sh[c + 3])) + u.w;
                }
            }
            int k0 = kq * 4;
            Ash[k0 + 0][m] = v.x;
            Ash[k0 + 1][m] = v.y;
            Ash[k0 + 2][m] = v.z;
            Ash[k0 + 3][m] = v.w;
        }
        #pragma unroll
        for (int j = 0; j < 8; j++) {
            int idx = tid + j * 384;
            int k = idx / 96, c = idx % 96;
            Wsh[k][c] = W[(kc + k) * 96 + c];
        }
        __syncthreads();
        #pragma unroll
        for (int k = 0; k < 32; k++) {
            float4 al = *(const float4*)&Ash[k][rg * 8];
            float4 ah = *(const float4*)&Ash[k][rg * 8 + 4];
            float4 w  = *(const float4*)&Wsh[k][cg * 4];
            float av[8] = {al.x, al.y, al.z, al.w, ah.x, ah.y, ah.z, ah.w};
            float wv[4] = {w.x, w.y, w.z, w.w};
            #pragma unroll
            for (int i = 0; i < 8; i++)
                #pragma unroll
                for (int j = 0; j < 4; j++)
                    acc[i][j] = fmaf(av[i], wv[j], acc[i][j]);
        }
        __syncthreads();
    }
    int c0 = cg * 4;
    float bv[4];
    #pragma unroll
    for (int j = 0; j < 4; j++) bv[j] = bias ? bias[c0 + j] : 0.f;
    float asv[4], adv[4];
    if (SCORES) {
        #pragma unroll
        for (int j = 0; j < 4; j++) { asv[j] = as_[c0 + j]; adv[j] = ad_[c0 + j]; }
    }
    int r0 = rowBase + rg * 8;
    #pragma unroll
    for (int i = 0; i < 8; i++) {
        int r = r0 + i;
        if (SCORES) {
            float s1 = acc[i][0] * asv[0] + acc[i][1] * asv[1] + acc[i][2] * asv[2] + acc[i][3] * asv[3];
            float s2 = acc[i][0] * adv[0] + acc[i][1] * adv[1] + acc[i][2] * adv[2] + acc[i][3] * adv[3];
            sSD[rg * 8 + i][cg] = make_float2(s1, s2);   // plain STS, no collisions
        }
        if (r < M) {
            float v0 = acc[i][0] + bv[0];
            float v1 = acc[i][1] + bv[1];
            float v2 = acc[i][2] + bv[2];
            float v3 = acc[i][3] + bv[3];
            if (ACT) { v0 = lrelu01(v0); v1 = lrelu01(v1); v2 = lrelu01(v2); v3 = lrelu01(v3); }
            float4 o = make_float4(v0, v1, v2, v3);
            *(float4*)&C[r * 96 + c0] = o;
            if (DUP) *(float4*)&C2[r * 96 + c0] = o;
        }
    }
    if (SCORES) {
        __syncthreads();
        if (tid < 128) {
            float s1 = 0.f, s2 = 0.f;
            #pragma unroll
            for (int c = 0; c < 24; c++) {
                float2 v = sSD[tid][c];
                s1 += v.x; s2 += v.y;
            }
            int r = rowBase + tid;
            if (r < M) { ssO[r] = s1; sdO[r] = s2; }
        }
    }
}

// ---------------- GAT aggregation: SINGLE PASS (warp/dst) + fused BN stats ----
// softmax normalization moved after the weighted sum: acc = sum(wv*row),
// denom = sum(wv), out = acc/denom.  Edge loop unrolled x2 with independent
// accumulator chains to double memory-level parallelism.
__global__ __launch_bounds__(512) void agg_k(
    const float* __restrict__ hp,
    const float* __restrict__ ss, const float* __restrict__ sd,
    const float* __restrict__ bias, float* __restrict__ out,
    float* __restrict__ sumP, float* __restrict__ sqP)
{
    __shared__ float bw0[16][96];
    __shared__ float bw1[16][96];
    int tid = threadIdx.x;
    int warp = tid >> 5, lane = tid & 31;
    int d = (blockIdx.x * blockDim.x + tid) >> 5;
    float v0 = 0.f, v1 = 0.f, v2 = 0.f;
    if (d < Nn) {
        int j = g_rs[d], s1e = g_rs[d + 1];
        float sdd = sd[d];
        float dA = 0.f, dB = 0.f;
        float a0A = 0.f, a1A = 0.f, a2A = 0.f;
        float a0B = 0.f, a1B = 0.f, a2B = 0.f;
        for (; j + 2 <= s1e; j += 2) {
            int sA = g_csr[j], sB = g_csr[j + 1];      // warp-uniform broadcast
            float eA = ss[sA] + sdd;
            float eB = ss[sB] + sdd;
            eA = (eA >= 0.f) ? eA : 0.2f * eA;
            eB = (eB >= 0.f) ? eB : 0.2f * eB;
            float wA = __expf(eA), wB = __expf(eB);
            const float* rA = hp + sA * 96;
            const float* rB = hp + sB * 96;
            dA += wA;  dB += wB;
            a0A = fmaf(wA, rA[lane], a0A);
            a0B = fmaf(wB, rB[lane], a0B);
            a1A = fmaf(wA, rA[lane + 32], a1A);
            a1B = fmaf(wB, rB[lane + 32], a1B);
            a2A = fmaf(wA, rA[lane + 64], a2A);
            a2B = fmaf(wB, rB[lane + 64], a2B);
        }
        if (j < s1e) {
            int sA = g_csr[j];
            float eA = ss[sA] + sdd;
            eA = (eA >= 0.f) ? eA : 0.2f * eA;
            float wA = __expf(eA);
            const float* rA = hp + sA * 96;
            dA += wA;
            a0A = fmaf(wA, rA[lane], a0A);
            a1A = fmaf(wA, rA[lane + 32], a1A);
            a2A = fmaf(wA, rA[lane + 64], a2A);
        }
        float inv = 1.f / (dA + dB);
        v0 = (a0A + a0B) * inv + bias[lane];
        v1 = (a1A + a1B) * inv + bias[lane + 32];
        v2 = (a2A + a2B) * inv + bias[lane + 64];
        out[d * 96 + lane]      = v0;
        out[d * 96 + lane + 32] = v1;
        out[d * 96 + lane + 64] = v2;
    }
    // atomic-free BN stats: per-warp channel partials, block tree-sum
    bw0[warp][lane]      = v0;       bw1[warp][lane]      = v0 * v0;
    bw0[warp][lane + 32] = v1;       bw1[warp][lane + 32] = v1 * v1;
    bw0[warp][lane + 64] = v2;       bw1[warp][lane + 64] = v2 * v2;
    __syncthreads();
    if (tid < 96) {
        float s = 0.f, q = 0.f;
        #pragma unroll
        for (int w = 0; w < 16; w++) { s += bw0[w][tid]; q += bw1[w][tid]; }
        atomicAdd(&sumP[tid], s);
        atomicAdd(&sqP[tid], q);
    }
}

// ---------------- fused BN-apply + Poincare expmap0 + segment pooling ----------------
__global__ void expool_k(const float* __restrict__ t, const float* __restrict__ idn,
                         const float* __restrict__ gma, const float* __restrict__ bta,
                         const float* __restrict__ sumP, const float* __restrict__ sqP,
                         const int* __restrict__ batch)
{
    __shared__ float sp[Gg * Hh];
    __shared__ float scn[Gg];
    __shared__ float s_sc[96], s_sh[96];
    if (threadIdx.x < 96) {
        int c = threadIdx.x;
        float mu = sumP[c] * (1.f / Nn);
        float var = sqP[c] * (1.f / Nn) - mu * mu;
        float is = rsqrtf(var + BNEPS);
        float gv = gma[c];
        s_sc[c] = gv * is;
        s_sh[c] = bta[c] - mu * gv * is;
    }
    for (int i = threadIdx.x; i < Gg * Hh; i += blockDim.x) sp[i] = 0.f;
    if (threadIdx.x < Gg) scn[threadIdx.x] = 0.f;
    __syncthreads();
    int lane = threadIdx.x & 31;
    int warp = (blockIdx.x * blockDim.x + threadIdx.x) >> 5;
    int nwarps = (gridDim.x * blockDim.x) >> 5;
    for (int n = warp; n < Nn; n += nwarps) {
        float v0 = lrelu01(fmaf(t[n * 96 + lane],      s_sc[lane],      s_sh[lane]))      + idn[n * 96 + lane];
        float v1 = lrelu01(fmaf(t[n * 96 + lane + 32], s_sc[lane + 32], s_sh[lane + 32])) + idn[n * 96 + lane + 32];
        float v2 = lrelu01(fmaf(t[n * 96 + lane + 64], s_sc[lane + 64], s_sh[lane + 64])) + idn[n * 96 + lane + 64];
        float q = v0 * v0 + v1 * v1 + v2 * v2;
        #pragma unroll
        for (int o = 16; o; o >>= 1) q += __shfl_xor_sync(0xffffffffu, q, o);
        float nrm = fmaxf(sqrtf(q), 1e-15f);
        float s = tanhf(nrm) / nrm;
        int g = batch[n];
        atomicAdd(&sp[g * 96 + lane], v0 * s);
        atomicAdd(&sp[g * 96 + lane + 32], v1 * s);
        atomicAdd(&sp[g * 96 + lane + 64], v2 * s);
        if (lane == 0) atomicAdd(&scn[g], 1.f);
    }
    __syncthreads();
    for (int i = threadIdx.x; i < Gg * Hh; i += blockDim.x) atomicAdd(&g_pooled[i], sp[i]);
    if (threadIdx.x < Gg) atomicAdd(&g_cnt[threadIdx.x], scn[threadIdx.x]);
}

// ---------------- head ----------------
__global__ void head_k(const float* __restrict__ fc3W, const float* __restrict__ fc3b,
                       const float* __restrict__ fc4W, const float* __restrict__ fc4b,
                       float* __restrict__ out)
{
    __shared__ float p[Gg * Hh];
    __shared__ float o1[Gg * 48];
    for (int i = threadIdx.x; i < Gg * Hh; i += blockDim.x) {
        int g = i / 96;
        p[i] = g_pooled[i] / fmaxf(g_cnt[g], 1.f);
    }
    __syncthreads();
    for (int i = threadIdx.x; i < Gg * 48; i += blockDim.x) {
        int g = i / 48, c = i % 48;
        float a = fc3b[c];
        for (int k = 0; k < 96; k++) a = fmaf(p[g * 96 + k], fc3W[k * 48 + c], a);
        o1[i] = lrelu01(a);
    }
    __syncthreads();
    for (int i = threadIdx.x; i < Gg * NCLS; i += blockDim.x) {
        int g = i / NCLS, c = i % NCLS;
        float a = fc4b[c];
        for (int k = 0; k < 48; k++) a = fmaf(o1[g * 48 + k], fc4W[k * NCLS + c], a);
        out[i] = a;
    }
}

// ---------------- launch ----------------
extern "C" void kernel_launch(void* const* d_in, const int* in_sizes, int n_in,
                              void* d_out, int out_size)
{
    const float* x     = (const float*)d_in[0];
    const int*   ei    = (const int*)d_in[1];
    const int*   batch = (const int*)d_in[2];
    const float* embW  = (const float*)d_in[3];
    const float* embB  = (const float*)d_in[4];
    const float* cW[3]  = {(const float*)d_in[5],  (const float*)d_in[9],  (const float*)d_in[13]};
    const float* cAS[3] = {(const float*)d_in[6],  (const float*)d_in[10], (const float*)d_in[14]};
    const float* cAD[3] = {(const float*)d_in[7],  (const float*)d_in[11], (const float*)d_in[15]};
    const float* cB[3]  = {(const float*)d_in[8],  (const float*)d_in[12], (const float*)d_in[16]};
    const float* fcW[2] = {(const float*)d_in[17], (const float*)d_in[19]};
    const float* fcB[2] = {(const float*)d_in[18], (const float*)d_in[20]};
    const float* bnG[3] = {(const float*)d_in[21], (const float*)d_in[23], (const float*)d_in[25]};
    const float* bnB[3] = {(const float*)d_in[22], (const float*)d_in[24], (const float*)d_in[26]};
    const float* fc3W = (const float*)d_in[27];
    const float* fc3b = (const float*)d_in[28];
    const float* fc4W = (const float*)d_in[29];
    const float* fc4b = (const float*)d_in[30];
    float* out = (float*)d_out;

    float *ph, *pid, *php, *ptmp, *pss, *psd, *pbs, *pbq;
    cudaGetSymbolAddress((void**)&ph,   g_h);
    cudaGetSymbolAddress((void**)&pid,  g_id);
    cudaGetSymbolAddress((void**)&php,  g_hp);
    cudaGetSymbolAddress((void**)&ptmp, g_tmp);
    cudaGetSymbolAddress((void**)&pss,  g_ss);
    cudaGetSymbolAddress((void**)&psd,  g_sd);
    cudaGetSymbolAddress((void**)&pbs,  g_bnsum);
    cudaGetSymbolAddress((void**)&pbq,  g_bnsq);

    const int EB = (ETOT + 255) / 256;
    const int GB = (Nn + 127) / 128;
    const int AB = (Nn * 32 + 511) / 512;

    // Fork: CSR build concurrent with embed GEMM. Streams/events intentionally
    // leaked (destroying them mid-capture would abort graph capture).
    cudaStream_t s1;
    cudaStreamCreateWithFlags(&s1, cudaStreamNonBlocking);
    cudaEvent_t evFork, evJoin;
    cudaEventCreateWithFlags(&evFork, cudaEventDisableTiming);
    cudaEventCreateWithFlags(&evJoin, cudaEventDisableTiming);

    cudaEventRecord(evFork, 0);
    cudaStreamWaitEvent(s1, evFork, 0);
    zero_k<<<256, 256, 0, s1>>>();
    count_k<<<EB, 256, 0, s1>>>(ei);
    scan_k<<<1, 1024, 0, s1>>>();
    scatter_k<<<EB, 256, 0, s1>>>(ei);
    cudaEventRecord(evJoin, s1);

    // embed: h = lrelu(x @ embW + embB); identity = h
    gemm128<1, 0, 1, 0><<<GB, 384>>>(x, nullptr, nullptr, nullptr, nullptr, nullptr,
                                     embW, embB, nullptr, nullptr, nullptr, nullptr,
                                     ph, pid, Nn, 256);

    for (int l = 0; l < 3; l++) {
        // hp = h @ cW  (+ fused atomic-free attention scores)
        gemm128<0, 0, 0, 1><<<GB, 384>>>(ph, nullptr, nullptr, nullptr, nullptr, nullptr,
                                         cW[l], nullptr, cAS[l], cAD[l], pss, psd,
                                         php, nullptr, Nn, 96);
        if (l == 0) cudaStreamWaitEvent(0, evJoin, 0);   // CSR + zeroed BN slots ready
        agg_k<<<AB, 512>>>(php, pss, psd, cB[l], ptmp, pbs + l * Hh, pbq + l * Hh);
        if (l < 2) {
            // h = lrelu( (lrelu(bn(tmp)) + id) @ fcW + fcB ) — BN fused into A-load
            gemm128<1, 1, 0, 0><<<GB, 384>>>(ptmp, pid, bnG[l], bnB[l], pbs + l * Hh, pbq + l * Hh,
                                             fcW[l], fcB[l], nullptr, nullptr, nullptr, nullptr,
                                             ph, nullptr, Nn, 96);
        }
    }

    expool_k<<<160, 256>>>(ptmp, pid, bnG[2], bnB[2], pbs + 2 * Hh, pbq + 2 * Hh, batch);
    head_k<<<1, 256>>>(fc3W, fc3b, fc4W, fc4b, out);
}

// round 12
// speedup vs baseline: 1.2335x; 1.0238x over previous
#include <cuda_runtime.h>
#include <math.h>

#define Nn 50000
#define Ee 800000
#define ETOT 850000
#define Hh 96
#define Gg 64
#define NCLS 4
#define BNEPS 1e-5f

// ---------------- device scratch ----------------
__device__ float g_h[Nn * Hh];
__device__ float g_id[Nn * Hh];
__device__ float g_hp[Nn * Hh];
__device__ float g_tmp[Nn * Hh];
__device__ float g_ss[Nn], g_sd[Nn];
__device__ int   g_deg[Nn];
__device__ int   g_rs[Nn + 1];
__device__ int   g_cur[Nn];
__device__ int   g_csr[ETOT];
__device__ float g_bnsum[3 * Hh], g_bnsq[3 * Hh];
__device__ float g_pooled[Gg * Hh];
__device__ float g_cnt[Gg];

__device__ __forceinline__ float lrelu01(float v) { return v >= 0.f ? v : 0.01f * v; }

// ---------------- zero / init ----------------
__global__ void zero_k() {
    int i = blockIdx.x * blockDim.x + threadIdx.x;
    int stride = gridDim.x * blockDim.x;
    for (int j = i; j < Nn; j += stride) g_deg[j] = 0;
    if (i < Gg * Hh) g_pooled[i] = 0.f;
    if (i < Gg) g_cnt[i] = 0.f;
    if (i < 3 * Hh) { g_bnsum[i] = 0.f; g_bnsq[i] = 0.f; }
}

// ---------------- CSR build ----------------
__global__ void count_k(const int* __restrict__ ei) {
    int i = blockIdx.x * blockDim.x + threadIdx.x;
    if (i >= ETOT) return;
    int d = (i < Ee) ? ei[Ee + i] : (i - Ee);
    atomicAdd(&g_deg[d], 1);
}

__global__ void scan_k() {
    __shared__ int part[1024];
    int t = threadIdx.x;
    const int CH = (Nn + 1023) / 1024;
    int base = t * CH;
    int s = 0;
    for (int i = 0; i < CH; i++) {
        int idx = base + i;
        if (idx < Nn) s += g_deg[idx];
    }
    part[t] = s;
    __syncthreads();
    for (int off = 1; off < 1024; off <<= 1) {
        int v = (t >= off) ? part[t - off] : 0;
        __syncthreads();
        part[t] += v;
        __syncthreads();
    }
    int run = (t == 0) ? 0 : part[t - 1];
    for (int i = 0; i < CH; i++) {
        int idx = base + i;
        if (idx < Nn) {
            g_rs[idx] = run;
            g_cur[idx] = run;
            run += g_deg[idx];
        }
    }
    if (t == blockDim.x - 1) g_rs[Nn] = part[blockDim.x - 1];
}

__global__ void scatter_k(const int* __restrict__ ei) {
    int i = blockIdx.x * blockDim.x + threadIdx.x;
    if (i >= ETOT) return;
    int sN, dN;
    if (i < Ee) { sN = ei[i]; dN = ei[Ee + i]; }
    else        { sN = i - Ee; dN = i - Ee; }
    int pos = atomicAdd(&g_cur[dN], 1);
    g_csr[pos] = sN;
}

// ---------------- embed GEMM (K=256): proven gemm128 core ----------------
__global__ __launch_bounds__(384, 2) void gemm128_emb(
    const float* __restrict__ A, const float* __restrict__ W,
    const float* __restrict__ bias,
    float* __restrict__ C, float* __restrict__ C2, int M, int K)
{
    __shared__ __align__(16) float Ash[32][132];
    __shared__ float Wsh[32][96];
    int tid = threadIdx.x;
    int cg = tid % 24;
    int rg = tid / 24;
    int rowBase = blockIdx.x * 128;
    float acc[8][4] = {};
    for (int kc = 0; kc < K; kc += 32) {
        for (int idx = tid; idx < 1024; idx += 384) {
            int m = idx >> 3, kq = idx & 7;
            int r = rowBase + m;
            float4 v = make_float4(0.f, 0.f, 0.f, 0.f);
            if (r < M) v = *(const float4*)&A[r * K + kc + kq * 4];
            int k0 = kq * 4;
            Ash[k0 + 0][m] = v.x;
            Ash[k0 + 1][m] = v.y;
            Ash[k0 + 2][m] = v.z;
            Ash[k0 + 3][m] = v.w;
        }
        #pragma unroll
        for (int j = 0; j < 8; j++) {
            int idx = tid + j * 384;
            int k = idx / 96, c = idx % 96;
            Wsh[k][c] = W[(kc + k) * 96 + c];
        }
        __syncthreads();
        #pragma unroll
        for (int k = 0; k < 32; k++) {
            float4 al = *(const float4*)&Ash[k][rg * 8];
            float4 ah = *(const float4*)&Ash[k][rg * 8 + 4];
            float4 w  = *(const float4*)&Wsh[k][cg * 4];
            float av[8] = {al.x, al.y, al.z, al.w, ah.x, ah.y, ah.z, ah.w};
            float wv[4] = {w.x, w.y, w.z, w.w};
            #pragma unroll
            for (int i = 0; i < 8; i++)
                #pragma unroll
                for (int j = 0; j < 4; j++)
                    acc[i][j] = fmaf(av[i], wv[j], acc[i][j]);
        }
        __syncthreads();
    }
    int c0 = cg * 4;
    float bv[4];
    #pragma unroll
    for (int j = 0; j < 4; j++) bv[j] = bias[c0 + j];
    int r0 = rowBase + rg * 8;
    #pragma unroll
    for (int i = 0; i < 8; i++) {
        int r = r0 + i;
        if (r < M) {
            float v0 = lrelu01(acc[i][0] + bv[0]);
            float v1 = lrelu01(acc[i][1] + bv[1]);
            float v2 = lrelu01(acc[i][2] + bv[2]);
            float v3 = lrelu01(acc[i][3] + bv[3]);
            float4 o = make_float4(v0, v1, v2, v3);
            *(float4*)&C[r * 96 + c0] = o;
            *(float4*)&C2[r * 96 + c0] = o;
        }
    }
}

// ---------------- K=96 GEMM: W resident + double-buffered A ----------------
// C[M,96] = act(A'[M,96] @ W[96,96] + bias). tile 128x96, 384 thd, 8x4 utile.
// MODE==1: A' = lrelu(bn(A)) + A2 fused on load.
// SCORES==1: per-row ss/sd via atomic-free smem partial reduction (reuses Ash).
#define DSM96 (96 * 96 * 4 + 2 * 32 * 132 * 4)   // 36864 + 33792 = 70656
template <int ACT, int MODE, int SCORES>
__global__ __launch_bounds__(384, 2) void gemm96w(
    const float* __restrict__ A, const float* __restrict__ A2,
    const float* __restrict__ gma, const float* __restrict__ bta,
    const float* __restrict__ sumP, const float* __restrict__ sqP,
    const float* __restrict__ W, const float* __restrict__ bias,
    const float* __restrict__ as_, const float* __restrict__ ad_,
    float* __restrict__ ssO, float* __restrict__ sdO,
    float* __restrict__ C, int M)
{
    extern __shared__ __align__(16) float dsm[];
    float* Wsh = dsm;                                  // [96*96]
    float (*Ash)[32][132] = (float (*)[32][132])(dsm + 9216);   // [2][32][132]
    float2 (*sSD)[25] = (float2 (*)[25])(dsm + 9216);  // reuses Ash region
    __shared__ float s_sc[96], s_sh[96];
    int tid = threadIdx.x;
    // whole W resident (9216 floats, coalesced)
    #pragma unroll
    for (int j = 0; j < 24; j++) Wsh[tid + j * 384] = W[tid + j * 384];
    if (MODE == 1) {
        if (tid < 96) {
            float mu = sumP[tid] * (1.f / Nn);
            float var = sqP[tid] * (1.f / Nn) - mu * mu;
            float is = rsqrtf(var + BNEPS);
            float gv = gma[tid];
            s_sc[tid] = gv * is;
            s_sh[tid] = bta[tid] - mu * gv * is;
        }
        __syncthreads();   // s_sc/s_sh ready before any A transform
    }
    int cg = tid % 24;
    int rg = tid / 24;
    int rowBase = blockIdx.x * 128;
    float acc[8][4] = {};
    float4 pf[3];

    // A-chunk loader into registers (with optional BN+residual fuse)
    auto loadA = [&](int kc) {
        #pragma unroll
        for (int it = 0; it < 3; it++) {
            int idx = tid + it * 384;
            if (idx < 1024) {
                int m = idx >> 3, kq = idx & 7;
                int r = rowBase + m;
                float4 v = make_float4(0.f, 0.f, 0.f, 0.f);
                if (r < M) {
                    v = *(const float4*)&A[r * 96 + kc + kq * 4];
                    if (MODE == 1) {
                        float4 u = *(const float4*)&A2[r * 96 + kc + kq * 4];
                        int c = kc + kq * 4;
                        v.x = lrelu01(fmaf(v.x, s_sc[c + 0], s_sh[c + 0])) + u.x;
                        v.y = lrelu01(fmaf(v.y, s_sc[c + 1], s_sh[c + 1])) + u.y;
                        v.z = lrelu01(fmaf(v.z, s_sc[c + 2], s_sh[c + 2])) + u.z;
                        v.w = lrelu01(fmaf(v.w, s_sc[c + 3], s_sh[c + 3])) + u.w;
                    }
                }
                pf[it] = v;
            }
        }
    };
    auto stsA = [&](int buf) {
        #pragma unroll
        for (int it = 0; it < 3; it++) {
            int idx = tid + it * 384;
            if (idx < 1024) {
                int m = idx >> 3, kq = idx & 7;
                int k0 = kq * 4;
                Ash[buf][k0 + 0][m] = pf[it].x;
                Ash[buf][k0 + 1][m] = pf[it].y;
                Ash[buf][k0 + 2][m] = pf[it].z;
                Ash[buf][k0 + 3][m] = pf[it].w;
            }
        }
    };

    loadA(0);
    stsA(0);
    __syncthreads();   // also covers Wsh visibility
    #pragma unroll
    for (int c = 0; c < 3; c++) {
        if (c < 2) loadA((c + 1) * 32);    // LDGs in flight during compute
        int buf = c & 1;
        const float* wrow = Wsh + c * 32 * 96 + cg * 4;
        #pragma unroll
        for (int k = 0; k < 32; k++) {
            float4 al = *(const float4*)&Ash[buf][k][rg * 8];
            float4 ah = *(const float4*)&Ash[buf][k][rg * 8 + 4];
            float4 w  = *(const float4*)(wrow + k * 96);
            float av[8] = {al.x, al.y, al.z, al.w, ah.x, ah.y, ah.z, ah.w};
            float wv[4] = {w.x, w.y, w.z, w.w};
            #pragma unroll
            for (int i = 0; i < 8; i++)
                #pragma unroll
                for (int j = 0; j < 4; j++)
                    acc[i][j] = fmaf(av[i], wv[j], acc[i][j]);
        }
        if (c < 2) {
            stsA(buf ^ 1);     // target buffer last read in chunk c-1 (pre-sync)
            __syncthreads();
        }
    }
    __syncthreads();   // Ash dead; safe to alias as sSD

    int c0 = cg * 4;
    float bv[4];
    #pragma unroll
    for (int j = 0; j < 4; j++) bv[j] = bias ? bias[c0 + j] : 0.f;
    float asv[4], adv[4];
    if (SCORES) {
        #pragma unroll
        for (int j = 0; j < 4; j++) { asv[j] = as_[c0 + j]; adv[j] = ad_[c0 + j]; }
    }
    int r0 = rowBase + rg * 8;
    #pragma unroll
    for (int i = 0; i < 8; i++) {
        int r = r0 + i;
        if (SCORES) {
            float s1 = acc[i][0] * asv[0] + acc[i][1] * asv[1] + acc[i][2] * asv[2] + acc[i][3] * asv[3];
            float s2 = acc[i][0] * adv[0] + acc[i][1] * adv[1] + acc[i][2] * adv[2] + acc[i][3] * adv[3];
            sSD[rg * 8 + i][cg] = make_float2(s1, s2);   // plain STS, no collisions
        }
        if (r < M) {
            float v0 = acc[i][0] + bv[0];
            float v1 = acc[i][1] + bv[1];
            float v2 = acc[i][2] + bv[2];
            float v3 = acc[i][3] + bv[3];
            if (ACT) { v0 = lrelu01(v0); v1 = lrelu01(v1); v2 = lrelu01(v2); v3 = lrelu01(v3); }
            *(float4*)&C[r * 96 + c0] = make_float4(v0, v1, v2, v3);
        }
    }
    if (SCORES) {
        __syncthreads();
        if (tid < 128) {
            float s1 = 0.f, s2 = 0.f;
            #pragma unroll
            for (int c = 0; c < 24; c++) {
                float2 v = sSD[tid][c];
                s1 += v.x; s2 += v.y;
            }
            int r = rowBase + tid;
            if (r < M) { ssO[r] = s1; sdO[r] = s2; }
        }
    }
}

// ---------------- GAT aggregation: single pass (warp/dst) + fused BN stats ----
__global__ __launch_bounds__(512) void agg_k(
    const float* __restrict__ hp,
    const float* __restrict__ ss, const float* __restrict__ sd,
    const float* __restrict__ bias, float* __restrict__ out,
    float* __restrict__ sumP, float* __restrict__ sqP)
{
    __shared__ float bw0[16][96];
    __shared__ float bw1[16][96];
    int tid = threadIdx.x;
    int warp = tid >> 5, lane = tid & 31;
    int d = (blockIdx.x * blockDim.x + tid) >> 5;
    float v0 = 0.f, v1 = 0.f, v2 = 0.f;
    if (d < Nn) {
        int j = g_rs[d], s1e = g_rs[d + 1];
        float sdd = sd[d];
        float dA = 0.f, dB = 0.f;
        float a0A = 0.f, a1A = 0.f, a2A = 0.f;
        float a0B = 0.f, a1B = 0.f, a2B = 0.f;
        for (; j + 2 <= s1e; j += 2) {
            int sA = g_csr[j], sB = g_csr[j + 1];
            float eA = ss[sA] + sdd;
            float eB = ss[sB] + sdd;
            eA = (eA >= 0.f) ? eA : 0.2f * eA;
            eB = (eB >= 0.f) ? eB : 0.2f * eB;
            float wA = __expf(eA), wB = __expf(eB);
            const float* rA = hp + sA * 96;
            const float* rB = hp + sB * 96;
            dA += wA;  dB += wB;
            a0A = fmaf(wA, rA[lane], a0A);
            a0B = fmaf(wB, rB[lane], a0B);
            a1A = fmaf(wA, rA[lane + 32], a1A);
            a1B = fmaf(wB, rB[lane + 32], a1B);
            a2A = fmaf(wA, rA[lane + 64], a2A);
            a2B = fmaf(wB, rB[lane + 64], a2B);
        }
        if (j < s1e) {
            int sA = g_csr[j];
            float eA = ss[sA] + sdd;
            eA = (eA >= 0.f) ? eA : 0.2f * eA;
            float wA = __expf(eA);
            const float* rA = hp + sA * 96;
            dA += wA;
            a0A = fmaf(wA, rA[lane], a0A);
            a1A = fmaf(wA, rA[lane + 32], a1A);
            a2A = fmaf(wA, rA[lane + 64], a2A);
        }
        float inv = 1.f / (dA + dB);
        v0 = (a0A + a0B) * inv + bias[lane];
        v1 = (a1A + a1B) * inv + bias[lane + 32];
        v2 = (a2A + a2B) * inv + bias[lane + 64];
        out[d * 96 + lane]      = v0;
        out[d * 96 + lane + 32] = v1;
        out[d * 96 + lane + 64] = v2;
    }
    bw0[warp][lane]      = v0;       bw1[warp][lane]      = v0 * v0;
    bw0[warp][lane + 32] = v1;       bw1[warp][lane + 32] = v1 * v1;
    bw0[warp][lane + 64] = v2;       bw1[warp][lane + 64] = v2 * v2;
    __syncthreads();
    if (tid < 96) {
        float s = 0.f, q = 0.f;
        #pragma unroll
        for (int w = 0; w < 16; w++) { s += bw0[w][tid]; q += bw1[w][tid]; }
        atomicAdd(&sumP[tid], s);
        atomicAdd(&sqP[tid], q);
    }
}

// ---------------- fused BN-apply + Poincare expmap0 + segment pooling ----------------
__global__ void expool_k(const float* __restrict__ t, const float* __restrict__ idn,
                         const float* __restrict__ gma, const float* __restrict__ bta,
                         const float* __restrict__ sumP, const float* __restrict__ sqP,
                         const int* __restrict__ batch)
{
    __shared__ float sp[Gg * Hh];
    __shared__ float scn[Gg];
    __shared__ float s_sc[96], s_sh[96];
    if (threadIdx.x < 96) {
        int c = threadIdx.x;
        float mu = sumP[c] * (1.f / Nn);
        float var = sqP[c] * (1.f / Nn) - mu * mu;
        float is = rsqrtf(var + BNEPS);
        float gv = gma[c];
        s_sc[c] = gv * is;
        s_sh[c] = bta[c] - mu * gv * is;
    }
    for (int i = threadIdx.x; i < Gg * Hh; i += blockDim.x) sp[i] = 0.f;
    if (threadIdx.x < Gg) scn[threadIdx.x] = 0.f;
    __syncthreads();
    int lane = threadIdx.x & 31;
    int warp = (blockIdx.x * blockDim.x + threadIdx.x) >> 5;
    int nwarps = (gridDim.x * blockDim.x) >> 5;
    for (int n = warp; n < Nn; n += nwarps) {
        float v0 = lrelu01(fmaf(t[n * 96 + lane],      s_sc[lane],      s_sh[lane]))      + idn[n * 96 + lane];
        float v1 = lrelu01(fmaf(t[n * 96 + lane + 32], s_sc[lane + 32], s_sh[lane + 32])) + idn[n * 96 + lane + 32];
        float v2 = lrelu01(fmaf(t[n * 96 + lane + 64], s_sc[lane + 64], s_sh[lane + 64])) + idn[n * 96 + lane + 64];
        float q = v0 * v0 + v1 * v1 + v2 * v2;
        #pragma unroll
        for (int o = 16; o; o >>= 1) q += __shfl_xor_sync(0xffffffffu, q, o);
        float nrm = fmaxf(sqrtf(q), 1e-15f);
        float s = tanhf(nrm) / nrm;
        int g = batch[n];
        atomicAdd(&sp[g * 96 + lane], v0 * s);
        atomicAdd(&sp[g * 96 + lane + 32], v1 * s);
        atomicAdd(&sp[g * 96 + lane + 64], v2 * s);
        if (lane == 0) atomicAdd(&scn[g], 1.f);
    }
    __syncthreads();
    for (int i = threadIdx.x; i < Gg * Hh; i += blockDim.x) atomicAdd(&g_pooled[i], sp[i]);
    if (threadIdx.x < Gg) atomicAdd(&g_cnt[threadIdx.x], scn[threadIdx.x]);
}

// ---------------- head ----------------
__global__ void head_k(const float* __restrict__ fc3W, const float* __restrict__ fc3b,
                       const float* __restrict__ fc4W, const float* __restrict__ fc4b,
                       float* __restrict__ out)
{
    __shared__ float p[Gg * Hh];
    __shared__ float o1[Gg * 48];
    for (int i = threadIdx.x; i < Gg * Hh; i += blockDim.x) {
        int g = i / 96;
        p[i] = g_pooled[i] / fmaxf(g_cnt[g], 1.f);
    }
    __syncthreads();
    for (int i = threadIdx.x; i < Gg * 48; i += blockDim.x) {
        int g = i / 48, c = i % 48;
        float a = fc3b[c];
        for (int k = 0; k < 96; k++) a = fmaf(p[g * 96 + k], fc3W[k * 48 + c], a);
        o1[i] = lrelu01(a);
    }
    __syncthreads();
    for (int i = threadIdx.x; i < Gg * NCLS; i += blockDim.x) {
        int g = i / NCLS, c = i % NCLS;
        float a = fc4b[c];
        for (int k = 0; k < 48; k++) a = fmaf(o1[g * 48 + k], fc4W[k * NCLS + c], a);
        out[i] = a;
    }
}

// ---------------- launch ----------------
extern "C" void kernel_launch(void* const* d_in, const int* in_sizes, int n_in,
                              void* d_out, int out_size)
{
    const float* x     = (const float*)d_in[0];
    const int*   ei    = (const int*)d_in[1];
    const int*   batch = (const int*)d_in[2];
    const float* embW  = (const float*)d_in[3];
    const float* embB  = (const float*)d_in[4];
    const float* cW[3]  = {(const float*)d_in[5],  (const float*)d_in[9],  (const float*)d_in[13]};
    const float* cAS[3] = {(const float*)d_in[6],  (const float*)d_in[10], (const float*)d_in[14]};
    const float* cAD[3] = {(const float*)d_in[7],  (const float*)d_in[11], (const float*)d_in[15]};
    const float* cB[3]  = {(const float*)d_in[8],  (const float*)d_in[12], (const float*)d_in[16]};
    const float* fcW[2] = {(const float*)d_in[17], (const float*)d_in[19]};
    const float* fcB[2] = {(const float*)d_in[18], (const float*)d_in[20]};
    const float* bnG[3] = {(const float*)d_in[21], (const float*)d_in[23], (const float*)d_in[25]};
    const float* bnB[3] = {(const float*)d_in[22], (const float*)d_in[24], (const float*)d_in[26]};
    const float* fc3W = (const float*)d_in[27];
    const float* fc3b = (const float*)d_in[28];
    const float* fc4W = (const float*)d_in[29];
    const float* fc4b = (const float*)d_in[30];
    float* out = (float*)d_out;

    float *ph, *pid, *php, *ptmp, *pss, *psd, *pbs, *pbq;
    cudaGetSymbolAddress((void**)&ph,   g_h);
    cudaGetSymbolAddress((void**)&pid,  g_id);
    cudaGetSymbolAddress((void**)&php,  g_hp);
    cudaGetSymbolAddress((void**)&ptmp, g_tmp);
    cudaGetSymbolAddress((void**)&pss,  g_ss);
    cudaGetSymbolAddress((void**)&psd,  g_sd);
    cudaGetSymbolAddress((void**)&pbs,  g_bnsum);
    cudaGetSymbolAddress((void**)&pbq,  g_bnsq);

    const int EB = (ETOT + 255) / 256;
    const int GB = (Nn + 127) / 128;
    const int AB = (Nn * 32 + 511) / 512;

    cudaFuncSetAttribute(gemm96w<0, 0, 1>, cudaFuncAttributeMaxDynamicSharedMemorySize, DSM96);
    cudaFuncSetAttribute(gemm96w<1, 1, 0>, cudaFuncAttributeMaxDynamicSharedMemorySize, DSM96);

    // Fork: CSR build concurrent with embed GEMM. Streams/events intentionally
    // leaked (destroying them mid-capture would abort graph capture).
    cudaStream_t s1;
    cudaStreamCreateWithFlags(&s1, cudaStreamNonBlocking);
    cudaEvent_t evFork, evJoin;
    cudaEventCreateWithFlags(&evFork, cudaEventDisableTiming);
    cudaEventCreateWithFlags(&evJoin, cudaEventDisableTiming);

    cudaEventRecord(evFork, 0);
    cudaStreamWaitEvent(s1, evFork, 0);
    zero_k<<<256, 256, 0, s1>>>();
    count_k<<<EB, 256, 0, s1>>>(ei);
    scan_k<<<1, 1024, 0, s1>>>();
    scatter_k<<<EB, 256, 0, s1>>>(ei);
    cudaEventRecord(evJoin, s1);

    // embed: h = lrelu(x @ embW + embB); identity = h
    gemm128_emb<<<GB, 384>>>(x, embW, embB, ph, pid, Nn, 256);

    for (int l = 0; l < 3; l++) {
        // hp = h @ cW  (+ fused atomic-free attention scores)
        gemm96w<0, 0, 1><<<GB, 384, DSM96>>>(ph, nullptr, nullptr, nullptr, nullptr, nullptr,
                                             cW[l], nullptr, cAS[l], cAD[l], pss, psd,
                                             php, Nn);
        if (l == 0) cudaStreamWaitEvent(0, evJoin, 0);   // CSR + zeroed BN slots ready
        agg_k<<<AB, 512>>>(php, pss, psd, cB[l], ptmp, pbs + l * Hh, pbq + l * Hh);
        if (l < 2) {
            // h = lrelu( (lrelu(bn(tmp)) + id) @ fcW + fcB ) — BN fused into A-load
            gemm96w<1, 1, 0><<<GB, 384, DSM96>>>(ptmp, pid, bnG[l], bnB[l], pbs + l * Hh, pbq + l * Hh,
                                                 fcW[l], fcB[l], nullptr, nullptr, nullptr, nullptr,
                                                 ph, Nn);
        }
    }

    expool_k<<<160, 256>>>(ptmp, pid, bnG[2], bnB[2], pbs + 2 * Hh, pbq + 2 * Hh, batch);
    head_k<<<1, 256>>>(fc3W, fc3b, fc4W, fc4b, out);
}

// round 14
// speedup vs baseline: 1.2388x; 1.0044x over previous
#include <cuda_runtime.h>
#include <cuda_fp16.h>
#include <math.h>

#define Nn 50000
#define Ee 800000
#define ETOT 850000
#define Hh 96
#define Gg 64
#define NCLS 4
#define BNEPS 1e-5f

// ---------------- device scratch ----------------
__device__ float g_h[Nn * Hh];
__device__ float g_id[Nn * Hh];
__device__ __half g_hph[Nn * Hh];    // hp in fp16 (gather traffic halved)
__device__ float g_tmp[Nn * Hh];
__device__ float g_ss[Nn], g_sd[Nn];
__device__ int   g_deg[Nn];
__device__ int   g_rs[Nn + 1];
__device__ int   g_cur[Nn];
__device__ int   g_csr[ETOT];
__device__ float g_bnsum[3 * Hh], g_bnsq[3 * Hh];
__device__ float g_pooled[Gg * Hh];
__device__ float g_cnt[Gg];

__device__ __forceinline__ float lrelu01(float v) { return v >= 0.f ? v : 0.01f * v; }

// ---------------- zero / init ----------------
__global__ void zero_k() {
    int i = blockIdx.x * blockDim.x + threadIdx.x;
    int stride = gridDim.x * blockDim.x;
    for (int j = i; j < Nn; j += stride) g_deg[j] = 0;
    if (i < Gg * Hh) g_pooled[i] = 0.f;
    if (i < Gg) g_cnt[i] = 0.f;
    if (i < 3 * Hh) { g_bnsum[i] = 0.f; g_bnsq[i] = 0.f; }
}

// ---------------- CSR build ----------------
__global__ void count_k(const int* __restrict__ ei) {
    int i = blockIdx.x * blockDim.x + threadIdx.x;
    if (i >= ETOT) return;
    int d = (i < Ee) ? ei[Ee + i] : (i - Ee);
    atomicAdd(&g_deg[d], 1);
}

__global__ void scan_k() {
    __shared__ int part[1024];
    int t = threadIdx.x;
    const int CH = (Nn + 1023) / 1024;
    int base = t * CH;
    int s = 0;
    for (int i = 0; i < CH; i++) {
        int idx = base + i;
        if (idx < Nn) s += g_deg[idx];
    }
    part[t] = s;
    __syncthreads();
    for (int off = 1; off < 1024; off <<= 1) {
        int v = (t >= off) ? part[t - off] : 0;
        __syncthreads();
        part[t] += v;
        __syncthreads();
    }
    int run = (t == 0) ? 0 : part[t - 1];
    for (int i = 0; i < CH; i++) {
        int idx = base + i;
        if (idx < Nn) {
            g_rs[idx] = run;
            g_cur[idx] = run;
            run += g_deg[idx];
        }
    }
    if (t == blockDim.x - 1) g_rs[Nn] = part[blockDim.x - 1];
}

__global__ void scatter_k(const int* __restrict__ ei) {
    int i = blockIdx.x * blockDim.x + threadIdx.x;
    if (i >= ETOT) return;
    int sN, dN;
    if (i < Ee) { sN = ei[i]; dN = ei[Ee + i]; }
    else        { sN = i - Ee; dN = i - Ee; }
    int pos = atomicAdd(&g_cur[dN], 1);
    g_csr[pos] = sN;
}

// ---------------- embed GEMM (K=256): proven gemm128 core ----------------
__global__ __launch_bounds__(384, 2) void gemm128_emb(
    const float* __restrict__ A, const float* __restrict__ W,
    const float* __restrict__ bias,
    float* __restrict__ C, float* __restrict__ C2, int M, int K)
{
    __shared__ __align__(16) float Ash[32][132];
    __shared__ float Wsh[32][96];
    int tid = threadIdx.x;
    int cg = tid % 24;
    int rg = tid / 24;
    int rowBase = blockIdx.x * 128;
    float acc[8][4] = {};
    for (int kc = 0; kc < K; kc += 32) {
        for (int idx = tid; idx < 1024; idx += 384) {
            int m = idx >> 3, kq = idx & 7;
            int r = rowBase + m;
            float4 v = make_float4(0.f, 0.f, 0.f, 0.f);
            if (r < M) v = *(const float4*)&A[r * K + kc + kq * 4];
            int k0 = kq * 4;
            Ash[k0 + 0][m] = v.x;
            Ash[k0 + 1][m] = v.y;
            Ash[k0 + 2][m] = v.z;
            Ash[k0 + 3][m] = v.w;
        }
        #pragma unroll
        for (int j = 0; j < 8; j++) {
            int idx = tid + j * 384;
            int k = idx / 96, c = idx % 96;
            Wsh[k][c] = W[(kc + k) * 96 + c];
        }
        __syncthreads();
        #pragma unroll
        for (int k = 0; k < 32; k++) {
            float4 al = *(const float4*)&Ash[k][rg * 8];
            float4 ah = *(const float4*)&Ash[k][rg * 8 + 4];
            float4 w  = *(const float4*)&Wsh[k][cg * 4];
            float av[8] = {al.x, al.y, al.z, al.w, ah.x, ah.y, ah.z, ah.w};
            float wv[4] = {w.x, w.y, w.z, w.w};
            #pragma unroll
            for (int i = 0; i < 8; i++)
                #pragma unroll
                for (int j = 0; j < 4; j++)
                    acc[i][j] = fmaf(av[i], wv[j], acc[i][j]);
        }
        __syncthreads();
    }
    int c0 = cg * 4;
    float bv[4];
    #pragma unroll
    for (int j = 0; j < 4; j++) bv[j] = bias[c0 + j];
    int r0 = rowBase + rg * 8;
    #pragma unroll
    for (int i = 0; i < 8; i++) {
        int r = r0 + i;
        if (r < M) {
            float v0 = lrelu01(acc[i][0] + bv[0]);
            float v1 = lrelu01(acc[i][1] + bv[1]);
            float v2 = lrelu01(acc[i][2] + bv[2]);
            float v3 = lrelu01(acc[i][3] + bv[3]);
            float4 o = make_float4(v0, v1, v2, v3);
            *(float4*)&C[r * 96 + c0] = o;
            *(float4*)&C2[r * 96 + c0] = o;
        }
    }
}

// ---------------- K=96 GEMM: W resident + double-buffered A ----------------
// MODE==1: A' = lrelu(bn(A)) + A2 fused on load.
// SCORES==1: per-row ss/sd via atomic-free smem reduction; C written as fp16.
#define DSM96 (96 * 96 * 4 + 2 * 32 * 132 * 4)   // 70656
template <int ACT, int MODE, int SCORES>
__global__ __launch_bounds__(384, 2) void gemm96w(
    const float* __restrict__ A, const float* __restrict__ A2,
    const float* __restrict__ gma, const float* __restrict__ bta,
    const float* __restrict__ sumP, const float* __restrict__ sqP,
    const float* __restrict__ W, const float* __restrict__ bias,
    const float* __restrict__ as_, const float* __restrict__ ad_,
    float* __restrict__ ssO, float* __restrict__ sdO,
    void* __restrict__ Cv, int M)
{
    extern __shared__ __align__(16) float dsm[];
    float* Wsh = dsm;                                  // [96*96]
    float (*Ash)[32][132] = (float (*)[32][132])(dsm + 9216);   // [2][32][132]
    float2 (*sSD)[25] = (float2 (*)[25])(dsm + 9216);  // reuses Ash region
    __shared__ float s_sc[96], s_sh[96];
    int tid = threadIdx.x;
    #pragma unroll
    for (int j = 0; j < 24; j++) Wsh[tid + j * 384] = W[tid + j * 384];
    if (MODE == 1) {
        if (tid < 96) {
            float mu = sumP[tid] * (1.f / Nn);
            float var = sqP[tid] * (1.f / Nn) - mu * mu;
            float is = rsqrtf(var + BNEPS);
            float gv = gma[tid];
            s_sc[tid] = gv * is;
            s_sh[tid] = bta[tid] - mu * gv * is;
        }
        __syncthreads();
    }
    int cg = tid % 24;
    int rg = tid / 24;
    int rowBase = blockIdx.x * 128;
    float acc[8][4] = {};
    float4 pf[3];

    auto loadA = [&](int kc) {
        #pragma unroll
        for (int it = 0; it < 3; it++) {
            int idx = tid + it * 384;
            if (idx < 1024) {
                int m = idx >> 3, kq = idx & 7;
                int r = rowBase + m;
                float4 v = make_float4(0.f, 0.f, 0.f, 0.f);
                if (r < M) {
                    v = *(const float4*)&A[r * 96 + kc + kq * 4];
                    if (MODE == 1) {
                        float4 u = *(const float4*)&A2[r * 96 + kc + kq * 4];
                        int c = kc + kq * 4;
                        v.x = lrelu01(fmaf(v.x, s_sc[c + 0], s_sh[c + 0])) + u.x;
                        v.y = lrelu01(fmaf(v.y, s_sc[c + 1], s_sh[c + 1])) + u.y;
                        v.z = lrelu01(fmaf(v.z, s_sc[c + 2], s_sh[c + 2])) + u.z;
                        v.w = lrelu01(fmaf(v.w, s_sc[c + 3], s_sh[c + 3])) + u.w;
                    }
                }
                pf[it] = v;
            }
        }
    };
    auto stsA = [&](int buf) {
        #pragma unroll
        for (int it = 0; it < 3; it++) {
            int idx = tid + it * 384;
            if (idx < 1024) {
                int m = idx >> 3, kq = idx & 7;
                int k0 = kq * 4;
                Ash[buf][k0 + 0][m] = pf[it].x;
                Ash[buf][k0 + 1][m] = pf[it].y;
                Ash[buf][k0 + 2][m] = pf[it].z;
                Ash[buf][k0 + 3][m] = pf[it].w;
            }
        }
    };

    loadA(0);
    stsA(0);
    __syncthreads();
    #pragma unroll
    for (int c = 0; c < 3; c++) {
        if (c < 2) loadA((c + 1) * 32);
        int buf = c & 1;
        const float* wrow = Wsh + c * 32 * 96 + cg * 4;
        #pragma unroll
        for (int k = 0; k < 32; k++) {
            float4 al = *(const float4*)&Ash[buf][k][rg * 8];
            float4 ah = *(const float4*)&Ash[buf][k][rg * 8 + 4];
            float4 w  = *(const float4*)(wrow + k * 96);
            float av[8] = {al.x, al.y, al.z, al.w, ah.x, ah.y, ah.z, ah.w};
            float wv[4] = {w.x, w.y, w.z, w.w};
            #pragma unroll
            for (int i = 0; i < 8; i++)
                #pragma unroll
                for (int j = 0; j < 4; j++)
                    acc[i][j] = fmaf(av[i], wv[j], acc[i][j]);
        }
        if (c < 2) {
            stsA(buf ^ 1);
            __syncthreads();
        }
    }
    __syncthreads();   // Ash dead; safe to alias as sSD

    int c0 = cg * 4;
    float bv[4];
    #pragma unroll
    for (int j = 0; j < 4; j++) bv[j] = bias ? bias[c0 + j] : 0.f;
    float asv[4], adv[4];
    if (SCORES) {
        #pragma unroll
        for (int j = 0; j < 4; j++) { asv[j] = as_[c0 + j]; adv[j] = ad_[c0 + j]; }
    }
    int r0 = rowBase + rg * 8;
    #pragma unroll
    for (int i = 0; i < 8; i++) {
        int r = r0 + i;
        if (SCORES) {
            float s1 = acc[i][0] * asv[0] + acc[i][1] * asv[1] + acc[i][2] * asv[2] + acc[i][3] * asv[3];
            float s2 = acc[i][0] * adv[0] + acc[i][1] * adv[1] + acc[i][2] * adv[2] + acc[i][3] * adv[3];
            sSD[rg * 8 + i][cg] = make_float2(s1, s2);
        }
        if (r < M) {
            float v0 = acc[i][0] + bv[0];
            float v1 = acc[i][1] + bv[1];
            float v2 = acc[i][2] + bv[2];
            float v3 = acc[i][3] + bv[3];
            if (ACT) { v0 = lrelu01(v0); v1 = lrelu01(v1); v2 = lrelu01(v2); v3 = lrelu01(v3); }
            if (SCORES) {
                // fp16 output (halves the agg gather traffic)
                __half2 h01 = __floats2half2_rn(v0, v1);
                __half2 h23 = __floats2half2_rn(v2, v3);
                uint2 pk = make_uint2(*(unsigned*)&h01, *(unsigned*)&h23);
                *(uint2*)((__half*)Cv + r * 96 + c0) = pk;
            } else {
                *(float4*)((float*)Cv + r * 96 + c0) = make_float4(v0, v1, v2, v3);
            }
        }
    }
    if (SCORES) {
        __syncthreads();
        if (tid < 128) {
            float s1 = 0.f, s2 = 0.f;
            #pragma unroll
            for (int c = 0; c < 24; c++) {
                float2 v = sSD[tid][c];
                s1 += v.x; s2 += v.y;
            }
            int r = rowBase + tid;
            if (r < M) { ssO[r] = s1; sdO[r] = s2; }
        }
    }
}

// ---------------- GAT aggregation: single pass (warp/dst), fp16 gather ------
__global__ __launch_bounds__(512) void agg_k(
    const __half* __restrict__ hp,
    const float* __restrict__ ss, const float* __restrict__ sd,
    const float* __restrict__ bias, float* __restrict__ out,
    float* __restrict__ sumP, float* __restrict__ sqP)
{
    __shared__ float bw0[16][96];
    __shared__ float bw1[16][96];
    int tid = threadIdx.x;
    int warp = tid >> 5, lane = tid & 31;
    int d = (blockIdx.x * blockDim.x + tid) >> 5;
    float v0 = 0.f, v1 = 0.f, v2 = 0.f;
    if (d < Nn) {
        int j = g_rs[d], s1e = g_rs[d + 1];
        float sdd = sd[d];
        float dA = 0.f, dB = 0.f;
        float a0A = 0.f, a1A = 0.f, a2A = 0.f;
        float a0B = 0.f, a1B = 0.f, a2B = 0.f;
        for (; j + 2 <= s1e; j += 2) {
            int sA = g_csr[j], sB = g_csr[j + 1];
            float eA = ss[sA] + sdd;
            float eB = ss[sB] + sdd;
            eA = (eA >= 0.f) ? eA : 0.2f * eA;
            eB = (eB >= 0.f) ? eB : 0.2f * eB;
            float wA = __expf(eA), wB = __expf(eB);
            const __half* rA = hp + sA * 96;
            const __half* rB = hp + sB * 96;
            dA += wA;  dB += wB;
            a0A = fmaf(wA, __half2float(rA[lane]), a0A);
            a0B = fmaf(wB, __half2float(rB[lane]), a0B);
            a1A = fmaf(wA, __half2float(rA[lane + 32]), a1A);
            a1B = fmaf(wB, __half2float(rB[lane + 32]), a1B);
            a2A = fmaf(wA, __half2float(rA[lane + 64]), a2A);
            a2B = fmaf(wB, __half2float(rB[lane + 64]), a2B);
        }
        if (j < s1e) {
            int sA = g_csr[j];
            float eA = ss[sA] + sdd;
            eA = (eA >= 0.f) ? eA : 0.2f * eA;
            float wA = __expf(eA);
            const __half* rA = hp + sA * 96;
            dA += wA;
            a0A = fmaf(wA, __half2float(rA[lane]), a0A);
            a1A = fmaf(wA, __half2float(rA[lane + 32]), a1A);
            a2A = fmaf(wA, __half2float(rA[lane + 64]), a2A);
        }
        float inv = 1.f / (dA + dB);
        v0 = (a0A + a0B) * inv + bias[lane];
        v1 = (a1A + a1B) * inv + bias[lane + 32];
        v2 = (a2A + a2B) * inv + bias[lane + 64];
        out[d * 96 + lane]      = v0;
        out[d * 96 + lane + 32] = v1;
        out[d * 96 + lane + 64] = v2;
    }
    bw0[warp][lane]      = v0;       bw1[warp][lane]      = v0 * v0;
    bw0[warp][lane + 32] = v1;       bw1[warp][lane + 32] = v1 * v1;
    bw0[warp][lane + 64] = v2;       bw1[warp][lane + 64] = v2 * v2;
    __syncthreads();
    if (tid < 96) {
        float s = 0.f, q = 0.f;
        #pragma unroll
        for (int w = 0; w < 16; w++) { s += bw0[w][tid]; q += bw1[w][tid]; }
        atomicAdd(&sumP[tid], s);
        atomicAdd(&sqP[tid], q);
    }
}

// ---------------- fused BN-apply + Poincare expmap0 + segment pooling ----------------
__global__ void expool_k(const float* __restrict__ t, const float* __restrict__ idn,
                         const float* __restrict__ gma, const float* __restrict__ bta,
                         const float* __restrict__ sumP, const float* __restrict__ sqP,
                         const int* __restrict__ batch)
{
    __shared__ float sp[Gg * Hh];
    __shared__ float scn[Gg];
    __shared__ float s_sc[96], s_sh[96];
    if (threadIdx.x < 96) {
        int c = threadIdx.x;
        float mu = sumP[c] * (1.f / Nn);
        float var = sqP[c] * (1.f / Nn) - mu * mu;
        float is = rsqrtf(var + BNEPS);
        float gv = gma[c];
        s_sc[c] = gv * is;
        s_sh[c] = bta[c] - mu * gv * is;
    }
    for (int i = threadIdx.x; i < Gg * Hh; i += blockDim.x) sp[i] = 0.f;
    if (threadIdx.x < Gg) scn[threadIdx.x] = 0.f;
    __syncthreads();
    int lane = threadIdx.x & 31;
    int warp = (blockIdx.x * blockDim.x + threadIdx.x) >> 5;
    int nwarps = (gridDim.x * blockDim.x) >> 5;
    for (int n = warp; n < Nn; n += nwarps) {
        float v0 = lrelu01(fmaf(t[n * 96 + lane],      s_sc[lane],      s_sh[lane]))      + idn[n * 96 + lane];
        float v1 = lrelu01(fmaf(t[n * 96 + lane + 32], s_sc[lane + 32], s_sh[lane + 32])) + idn[n * 96 + lane + 32];
        float v2 = lrelu01(fmaf(t[n * 96 + lane + 64], s_sc[lane + 64], s_sh[lane + 64])) + idn[n * 96 + lane + 64];
        float q = v0 * v0 + v1 * v1 + v2 * v2;
        #pragma unroll
        for (int o = 16; o; o >>= 1) q += __shfl_xor_sync(0xffffffffu, q, o);
        float nrm = fmaxf(sqrtf(q), 1e-15f);
        float s = tanhf(nrm) / nrm;
        int g = batch[n];
        atomicAdd(&sp[g * 96 + lane], v0 * s);
        atomicAdd(&sp[g * 96 + lane + 32], v1 * s);
        atomicAdd(&sp[g * 96 + lane + 64], v2 * s);
        if (lane == 0) atomicAdd(&scn[g], 1.f);
    }
    __syncthreads();
    for (int i = threadIdx.x; i < Gg * Hh; i += blockDim.x) atomicAdd(&g_pooled[i], sp[i]);
    if (threadIdx.x < Gg) atomicAdd(&g_cnt[threadIdx.x], scn[threadIdx.x]);
}

// ---------------- head ----------------
__global__ void head_k(const float* __restrict__ fc3W, const float* __restrict__ fc3b,
                       const float* __restrict__ fc4W, const float* __restrict__ fc4b,
                       float* __restrict__ out)
{
    __shared__ float p[Gg * Hh];
    __shared__ float o1[Gg * 48];
    for (int i = threadIdx.x; i < Gg * Hh; i += blockDim.x) {
        int g = i / 96;
        p[i] = g_pooled[i] / fmaxf(g_cnt[g], 1.f);
    }
    __syncthreads();
    for (int i = threadIdx.x; i < Gg * 48; i += blockDim.x) {
        int g = i / 48, c = i % 48;
        float a = fc3b[c];
        for (int k = 0; k < 96; k++) a = fmaf(p[g * 96 + k], fc3W[k * 48 + c], a);
        o1[i] = lrelu01(a);
    }
    __syncthreads();
    for (int i = threadIdx.x; i < Gg * NCLS; i += blockDim.x) {
        int g = i / NCLS, c = i % NCLS;
        float a = fc4b[c];
        for (int k = 0; k < 48; k++) a = fmaf(o1[g * 48 + k], fc4W[k * NCLS + c], a);
        out[i] = a;
    }
}

// ---------------- launch ----------------
extern "C" void kernel_launch(void* const* d_in, const int* in_sizes, int n_in,
                              void* d_out, int out_size)
{
    const float* x     = (const float*)d_in[0];
    const int*   ei    = (const int*)d_in[1];
    const int*   batch = (const int*)d_in[2];
    const float* embW  = (const float*)d_in[3];
    const float* embB  = (const float*)d_in[4];
    const float* cW[3]  = {(const float*)d_in[5],  (const float*)d_in[9],  (const float*)d_in[13]};
    const float* cAS[3] = {(const float*)d_in[6],  (const float*)d_in[10], (const float*)d_in[14]};
    const float* cAD[3] = {(const float*)d_in[7],  (const float*)d_in[11], (const float*)d_in[15]};
    const float* cB[3]  = {(const float*)d_in[8],  (const float*)d_in[12], (const float*)d_in[16]};
    const float* fcW[2] = {(const float*)d_in[17], (const float*)d_in[19]};
    const float* fcB[2] = {(const float*)d_in[18], (const float*)d_in[20]};
    const float* bnG[3] = {(const float*)d_in[21], (const float*)d_in[23], (const float*)d_in[25]};
    const float* bnB[3] = {(const float*)d_in[22], (const float*)d_in[24], (const float*)d_in[26]};
    const float* fc3W = (const float*)d_in[27];
    const float* fc3b = (const float*)d_in[28];
    const float* fc4W = (const float*)d_in[29];
    const float* fc4b = (const float*)d_in[30];
    float* out = (float*)d_out;

    float *ph, *pid, *ptmp, *pss, *psd, *pbs, *pbq;
    __half* phph;
    cudaGetSymbolAddress((void**)&ph,   g_h);
    cudaGetSymbolAddress((void**)&pid,  g_id);
    cudaGetSymbolAddress((void**)&phph, g_hph);
    cudaGetSymbolAddress((void**)&ptmp, g_tmp);
    cudaGetSymbolAddress((void**)&pss,  g_ss);
    cudaGetSymbolAddress((void**)&psd,  g_sd);
    cudaGetSymbolAddress((void**)&pbs,  g_bnsum);
    cudaGetSymbolAddress((void**)&pbq,  g_bnsq);

    const int EB = (ETOT + 255) / 256;
    const int GB = (Nn + 127) / 128;
    const int AB = (Nn * 32 + 511) / 512;

    cudaFuncSetAttribute(gemm96w<0, 0, 1>, cudaFuncAttributeMaxDynamicSharedMemorySize, DSM96);
    cudaFuncSetAttribute(gemm96w<1, 1, 0>, cudaFuncAttributeMaxDynamicSharedMemorySize, DSM96);

    // Fork: CSR build concurrent with embed GEMM. Streams/events intentionally
    // leaked (destroying them mid-capture would abort graph capture).
    cudaStream_t s1;
    cudaStreamCreateWithFlags(&s1, cudaStreamNonBlocking);
    cudaEvent_t evFork, evJoin;
    cudaEventCreateWithFlags(&evFork, cudaEventDisableTiming);
    cudaEventCreateWithFlags(&evJoin, cudaEventDisableTiming);

    cudaEventRecord(evFork, 0);
    cudaStreamWaitEvent(s1, evFork, 0);
    zero_k<<<256, 256, 0, s1>>>();
    count_k<<<EB, 256, 0, s1>>>(ei);
    scan_k<<<1, 1024, 0, s1>>>();
    scatter_k<<<EB, 256, 0, s1>>>(ei);
    cudaEventRecord(evJoin, s1);

    // embed: h = lrelu(x @ embW + embB); identity = h
    gemm128_emb<<<GB, 384>>>(x, embW, embB, ph, pid, Nn, 256);

    for (int l = 0; l < 3; l++) {
        // hp(fp16) = h @ cW  (+ fused atomic-free attention scores)
        gemm96w<0, 0, 1><<<GB, 384, DSM96>>>(ph, nullptr, nullptr, nullptr, nullptr, nullptr,
                                             cW[l], nullptr, cAS[l], cAD[l], pss, psd,
                                             (void*)phph, Nn);
        if (l == 0) cudaStreamWaitEvent(0, evJoin, 0);   // CSR + zeroed BN slots ready
        agg_k<<<AB, 512>>>(phph, pss, psd, cB[l], ptmp, pbs + l * Hh, pbq + l * Hh);
        if (l < 2) {
            // h = lrelu( (lrelu(bn(tmp)) + id) @ fcW + fcB ) — BN fused into A-load
            gemm96w<1, 1, 0><<<GB, 384, DSM96>>>(ptmp, pid, bnG[l], bnB[l], pbs + l * Hh, pbq + l * Hh,
                                                 fcW[l], fcB[l], nullptr, nullptr, nullptr, nullptr,
                                                 (void*)ph, Nn);
        }
    }

    expool_k<<<160, 256>>>(ptmp, pid, bnG[2], bnB[2], pbs + 2 * Hh, pbq + 2 * Hh, batch);
    head_k<<<1, 256>>>(fc3W, fc3b, fc4W, fc4b, out);
}